// round 2
// baseline (speedup 1.0000x reference)
#include <cuda_runtime.h>
#include <math.h>
#include <stdint.h>

#define NN    100000
#define NE    1600000
#define D_INF 128
#define D_H   256
#define D_O   40
#define SCAN_BLOCKS ((NN + 1023) / 1024)

// ---------------- scratch (device globals; no allocation allowed) ----------
__device__ float g_bufA[(size_t)NN * D_H];   // features
__device__ float g_bufB[(size_t)NN * D_H];   // pre-scaled GEMM output (hs)
__device__ int   g_deg[NN];
__device__ float g_dinv[NN];
__device__ int   g_rowptr[NN + 1];
__device__ int   g_cursor[NN];
__device__ int   g_col[NE];
__device__ int   g_bsum[256];
__device__ float g_sum[D_H];
__device__ float g_sumsq[D_H];
__device__ float g_scale[D_H];
__device__ float g_shift[D_H];

// ---------------- graph preprocessing --------------------------------------
__global__ void zero_deg_kernel() {
    int i = blockIdx.x * blockDim.x + threadIdx.x;
    if (i < NN) g_deg[i] = 0;
}

__global__ void count_deg_kernel(const int* __restrict__ rowE) {
    int e = blockIdx.x * blockDim.x + threadIdx.x;
    if (e < NE) atomicAdd(&g_deg[rowE[e]], 1);
}

__global__ void scan1_kernel() {
    __shared__ int sm[1024];
    int tid = threadIdx.x;
    int i = blockIdx.x * 1024 + tid;
    int v = (i < NN) ? g_deg[i] : 0;
    int x = v;
    sm[tid] = x;
    __syncthreads();
    #pragma unroll
    for (int off = 1; off < 1024; off <<= 1) {
        int t = (tid >= off) ? sm[tid - off] : 0;
        __syncthreads();
        x += t;
        sm[tid] = x;
        __syncthreads();
    }
    if (i < NN) g_rowptr[i] = x - v;          // block-local exclusive
    if (tid == 1023) g_bsum[blockIdx.x] = x;  // block total
}

__global__ void scan2_kernel() {
    __shared__ int sm[128];
    int tid = threadIdx.x;
    int v = (tid < SCAN_BLOCKS) ? g_bsum[tid] : 0;
    int x = v;
    sm[tid] = x;
    __syncthreads();
    #pragma unroll
    for (int off = 1; off < 128; off <<= 1) {
        int t = (tid >= off) ? sm[tid - off] : 0;
        __syncthreads();
        x += t;
        sm[tid] = x;
        __syncthreads();
    }
    if (tid < SCAN_BLOCKS) g_bsum[tid] = x - v;  // exclusive block offsets
    if (tid == 127) g_rowptr[NN] = x;            // = NE
}

__global__ void scan3_kernel() {
    int i = blockIdx.x * blockDim.x + threadIdx.x;
    if (i >= NN) return;
    int rp = g_rowptr[i] + g_bsum[i >> 10];
    g_rowptr[i] = rp;
    g_cursor[i] = rp;
    g_dinv[i] = rsqrtf((float)(g_deg[i] + 1));   // +1 self loop
}

__global__ void fill_csr_kernel(const int* __restrict__ rowE,
                                const int* __restrict__ colE) {
    int e = blockIdx.x * blockDim.x + threadIdx.x;
    if (e >= NE) return;
    int r = rowE[e];
    int p = atomicAdd(&g_cursor[r], 1);
    g_col[p] = colE[e];
}

// ---------------- tiled SGEMM with dinv row-scaling epilogue ----------------
// C[r, 0:TN] = dinv[r] * (A[r, 0:TK] @ W[0:TK, 0:TN])
template <int TK, int TN>
__global__ __launch_bounds__(256)
void gemm_scale_kernel(const float* __restrict__ A,
                       const float* __restrict__ W,
                       float* __restrict__ C) {
    __shared__ float As[8][132];  // [k][row], padded
    __shared__ float Bs[8][128];  // [k][col]
    int tid = threadIdx.x;
    int rowBase = blockIdx.x * 128;
    int colBase = blockIdx.y * 128;
    int ty = tid >> 4, tx = tid & 15;
    int aRow = tid >> 1;
    int aK   = (tid & 1) * 4;
    int bK   = tid >> 5;
    int bCol = (tid & 31) * 4;

    float acc[8][8];
    #pragma unroll
    for (int i = 0; i < 8; ++i)
        #pragma unroll
        for (int j = 0; j < 8; ++j) acc[i][j] = 0.f;

    for (int k0 = 0; k0 < TK; k0 += 8) {
        float4 av = make_float4(0.f, 0.f, 0.f, 0.f);
        int gr = rowBase + aRow;
        if (gr < NN)
            av = *reinterpret_cast<const float4*>(A + (size_t)gr * TK + k0 + aK);
        As[aK + 0][aRow] = av.x;
        As[aK + 1][aRow] = av.y;
        As[aK + 2][aRow] = av.z;
        As[aK + 3][aRow] = av.w;

        float4 bv = make_float4(0.f, 0.f, 0.f, 0.f);
        int gc = colBase + bCol;
        if (gc < TN)
            bv = *reinterpret_cast<const float4*>(W + (size_t)(k0 + bK) * TN + gc);
        *reinterpret_cast<float4*>(&Bs[bK][bCol]) = bv;
        __syncthreads();

        #pragma unroll
        for (int kk = 0; kk < 8; ++kk) {
            float a[8], b[8];
            *reinterpret_cast<float4*>(&a[0]) = *reinterpret_cast<const float4*>(&As[kk][ty * 8]);
            *reinterpret_cast<float4*>(&a[4]) = *reinterpret_cast<const float4*>(&As[kk][ty * 8 + 4]);
            *reinterpret_cast<float4*>(&b[0]) = *reinterpret_cast<const float4*>(&Bs[kk][tx * 8]);
            *reinterpret_cast<float4*>(&b[4]) = *reinterpret_cast<const float4*>(&Bs[kk][tx * 8 + 4]);
            #pragma unroll
            for (int i = 0; i < 8; ++i)
                #pragma unroll
                for (int j = 0; j < 8; ++j)
                    acc[i][j] = fmaf(a[i], b[j], acc[i][j]);
        }
        __syncthreads();
    }

    #pragma unroll
    for (int i = 0; i < 8; ++i) {
        int r = rowBase + ty * 8 + i;
        if (r >= NN) continue;
        float s = g_dinv[r];
        #pragma unroll
        for (int j = 0; j < 8; j += 4) {
            int cc = colBase + tx * 8 + j;
            if (cc < TN) {
                float4 v = make_float4(acc[i][j] * s, acc[i][j + 1] * s,
                                       acc[i][j + 2] * s, acc[i][j + 3] * s);
                *reinterpret_cast<float4*>(C + (size_t)r * TN + cc) = v;
            }
        }
    }
}

// ---------------- SpMM (gather-only CSR), D=256, warp per row ---------------
// out[r] = dinv[r] * ( sum_{c in nbrs(r)} hs[c] + hs[r] )
__global__ __launch_bounds__(256)
void spmm256_kernel(const float* __restrict__ hs, float* __restrict__ out) {
    int warp = threadIdx.x >> 5, lane = threadIdx.x & 31;
    int row = blockIdx.x * 8 + warp;
    if (row >= NN) return;
    const float4* hs4 = reinterpret_cast<const float4*>(hs);
    size_t rbase = (size_t)row * 64;
    float4 a0 = hs4[rbase + lane];
    float4 a1 = hs4[rbase + 32 + lane];
    int s = g_rowptr[row], e = g_rowptr[row + 1];
    for (int i = s; i < e; ++i) {
        int c = g_col[i];
        size_t cbase = (size_t)c * 64;
        float4 v0 = hs4[cbase + lane];
        float4 v1 = hs4[cbase + 32 + lane];
        a0.x += v0.x; a0.y += v0.y; a0.z += v0.z; a0.w += v0.w;
        a1.x += v1.x; a1.y += v1.y; a1.z += v1.z; a1.w += v1.w;
    }
    float d = g_dinv[row];
    a0.x *= d; a0.y *= d; a0.z *= d; a0.w *= d;
    a1.x *= d; a1.y *= d; a1.z *= d; a1.w *= d;
    float4* out4 = reinterpret_cast<float4*>(out);
    out4[rbase + lane] = a0;
    out4[rbase + 32 + lane] = a1;
}

// ---------------- BatchNorm ------------------------------------------------
__global__ void zero_stats_kernel() {
    int c = threadIdx.x;
    g_sum[c] = 0.f;
    g_sumsq[c] = 0.f;
}

__global__ __launch_bounds__(256)
void bn_reduce_kernel(const float* __restrict__ y) {
    int c = threadIdx.x;
    int r0 = blockIdx.x * 128;
    int rend = min(r0 + 128, NN);
    float s = 0.f, ss = 0.f;
    for (int r = r0; r < rend; ++r) {
        float v = y[(size_t)r * D_H + c];
        s += v;
        ss += v * v;
    }
    atomicAdd(&g_sum[c], s);
    atomicAdd(&g_sumsq[c], ss);
}

__global__ void bn_finalize_kernel(const float* __restrict__ gamma,
                                   const float* __restrict__ beta) {
    int c = threadIdx.x;
    float mu = g_sum[c] * (1.f / NN);
    float var = g_sumsq[c] * (1.f / NN) - mu * mu;
    float rstd = rsqrtf(var + 1e-5f);
    float sc = rstd * gamma[c];
    g_scale[c] = sc;
    g_shift[c] = beta[c] - mu * sc;
}

__global__ __launch_bounds__(256)
void bn_apply_kernel(float* __restrict__ y) {
    size_t i = (size_t)blockIdx.x * blockDim.x + threadIdx.x;  // float4 index
    const size_t total = (size_t)NN * 64;
    if (i >= total) return;
    int c4 = ((int)(i & 63)) * 4;
    float4 v = reinterpret_cast<float4*>(y)[i];
    v.x = fmaxf(fmaf(v.x, g_scale[c4 + 0], g_shift[c4 + 0]), 0.f);
    v.y = fmaxf(fmaf(v.y, g_scale[c4 + 1], g_shift[c4 + 1]), 0.f);
    v.z = fmaxf(fmaf(v.z, g_scale[c4 + 2], g_shift[c4 + 2]), 0.f);
    v.w = fmaxf(fmaf(v.w, g_scale[c4 + 3], g_shift[c4 + 3]), 0.f);
    reinterpret_cast<float4*>(y)[i] = v;
}

// ---------------- final SpMM (D=40) + bias + log_softmax -------------------
__global__ __launch_bounds__(256)
void spmm40_softmax_kernel(const float* __restrict__ hs,
                           const float* __restrict__ bl,
                           float* __restrict__ out) {
    int warp = threadIdx.x >> 5, lane = threadIdx.x & 31;
    int row = blockIdx.x * 8 + warp;
    if (row >= NN) return;
    size_t rbase = (size_t)row * D_O;
    float a0 = hs[rbase + lane];                       // cols 0..31
    float a1 = (lane < 8) ? hs[rbase + 32 + lane] : 0.f;  // cols 32..39
    int s = g_rowptr[row], e = g_rowptr[row + 1];
    for (int i = s; i < e; ++i) {
        int c = g_col[i];
        size_t cb = (size_t)c * D_O;
        a0 += hs[cb + lane];
        if (lane < 8) a1 += hs[cb + 32 + lane];
    }
    float d = g_dinv[row];
    float v0 = fmaf(a0, d, bl[lane]);
    float v1 = (lane < 8) ? fmaf(a1, d, bl[32 + lane]) : 0.f;

    float m = v0;
    if (lane < 8) m = fmaxf(m, v1);
    #pragma unroll
    for (int off = 16; off > 0; off >>= 1)
        m = fmaxf(m, __shfl_xor_sync(0xffffffffu, m, off));
    float sum = expf(v0 - m) + ((lane < 8) ? expf(v1 - m) : 0.f);
    #pragma unroll
    for (int off = 16; off > 0; off >>= 1)
        sum += __shfl_xor_sync(0xffffffffu, sum, off);
    float lse = logf(sum);
    out[rbase + lane] = v0 - m - lse;
    if (lane < 8) out[rbase + 32 + lane] = v1 - m - lse;
}

// ---------------- launcher --------------------------------------------------
extern "C" void kernel_launch(void* const* d_in, const int* in_sizes, int n_in,
                              void* d_out, int out_size) {
    const float* x     = (const float*)d_in[0];   // [NN, 128]
    const float* W0    = (const float*)d_in[1];   // [128, 256]
    const float* Wh    = (const float*)d_in[3];   // [3, 256, 256]
    const float* gamma = (const float*)d_in[5];   // [4, 256]
    const float* beta  = (const float*)d_in[6];   // [4, 256]
    const float* Wl    = (const float*)d_in[7];   // [256, 40]
    const float* bl    = (const float*)d_in[8];   // [40]
    const int* ei      = (const int*)d_in[9];     // [2, NE] int32 (JAX x64 disabled)
    const int* rowE = ei;
    const int* colE = ei + NE;
    float* out = (float*)d_out;

    float *pA = nullptr, *pB = nullptr;
    cudaGetSymbolAddress((void**)&pA, g_bufA);
    cudaGetSymbolAddress((void**)&pB, g_bufB);

    const int EB = (NE + 255) / 256;
    const int NBLK = (NN + 255) / 256;
    dim3 gemmGrid256((NN + 127) / 128, 2);
    dim3 gemmGrid40((NN + 127) / 128, 1);
    int spmmGrid = (NN + 7) / 8;
    int bnRedGrid = (NN + 127) / 128;
    int bnAppGrid = (int)(((size_t)NN * 64 + 255) / 256);

    // graph preprocessing: degree -> dinv, CSR
    zero_deg_kernel<<<NBLK, 256>>>();
    count_deg_kernel<<<EB, 256>>>(rowE);
    scan1_kernel<<<SCAN_BLOCKS, 1024>>>();
    scan2_kernel<<<1, 128>>>();
    scan3_kernel<<<NBLK, 256>>>();
    fill_csr_kernel<<<EB, 256>>>(rowE, colE);

    // layer 0: x @ W0 (bias cancels under BN)
    gemm_scale_kernel<D_INF, D_H><<<gemmGrid256, 256>>>(x, W0, pB);
    spmm256_kernel<<<spmmGrid, 256>>>(pB, pA);
    zero_stats_kernel<<<1, 256>>>();
    bn_reduce_kernel<<<bnRedGrid, 256>>>(pA);
    bn_finalize_kernel<<<1, 256>>>(gamma, beta);
    bn_apply_kernel<<<bnAppGrid, 256>>>(pA);

    // hidden layers 1..3
    for (int l = 0; l < 3; ++l) {
        gemm_scale_kernel<D_H, D_H><<<gemmGrid256, 256>>>(pA, Wh + (size_t)l * D_H * D_H, pB);
        spmm256_kernel<<<spmmGrid, 256>>>(pB, pA);
        zero_stats_kernel<<<1, 256>>>();
        bn_reduce_kernel<<<bnRedGrid, 256>>>(pA);
        bn_finalize_kernel<<<1, 256>>>(gamma + (size_t)(l + 1) * D_H,
                                       beta + (size_t)(l + 1) * D_H);
        bn_apply_kernel<<<bnAppGrid, 256>>>(pA);
    }

    // final layer + log_softmax
    gemm_scale_kernel<D_H, D_O><<<gemmGrid40, 256>>>(pA, Wl, pB);
    spmm40_softmax_kernel<<<spmmGrid, 256>>>(pB, bl, out);
}

// round 4
// speedup vs baseline: 1.4739x; 1.4739x over previous
#include <cuda_runtime.h>
#include <cuda_bf16.h>
#include <math.h>
#include <stdint.h>

#define NN    100000
#define NE    1600000
#define D_INF 128
#define D_H   256
#define D_O   40
#define SCAN_BLOCKS ((NN + 1023) / 1024)

// ---------------- scratch (device globals; no allocation allowed) ----------
__device__ float g_bufA[(size_t)NN * D_H];
__device__ float g_bufB[(size_t)NN * D_H];
__device__ int   g_deg[NN];
__device__ float g_dinv[NN];
__device__ int   g_rowptr[NN + 1];
__device__ int   g_cursor[NN];
__device__ int   g_col[NE];
__device__ int   g_bsum[256];
__device__ float g_sum[D_H];
__device__ float g_sumsq[D_H];
__device__ float g_scale[D_H];
__device__ float g_shift[D_H];
// bf16 split weights, transposed to [N][K]
__device__ __nv_bfloat16 g_w0hi[256 * 128];
__device__ __nv_bfloat16 g_w0lo[256 * 128];
__device__ __nv_bfloat16 g_whhi[3 * 256 * 256];
__device__ __nv_bfloat16 g_whlo[3 * 256 * 256];

// ---------------- helpers ----------------------------------------------------
__device__ __forceinline__ uint32_t smem_u32(const void* p) {
    uint32_t a;
    asm("{ .reg .u64 t; cvta.to.shared.u64 t, %1; cvt.u32.u64 %0, t; }" : "=r"(a) : "l"(p));
    return a;
}
#define SW128(o) ((o) ^ (((o) >> 3) & 0x70))

__device__ __forceinline__ void ldm_x4(uint32_t* r, uint32_t addr) {
    asm volatile("ldmatrix.sync.aligned.m8n8.x4.shared.b16 {%0,%1,%2,%3}, [%4];"
                 : "=r"(r[0]), "=r"(r[1]), "=r"(r[2]), "=r"(r[3]) : "r"(addr));
}
__device__ __forceinline__ void ldm_x2(uint32_t& r0, uint32_t& r1, uint32_t addr) {
    asm volatile("ldmatrix.sync.aligned.m8n8.x2.shared.b16 {%0,%1}, [%2];"
                 : "=r"(r0), "=r"(r1) : "r"(addr));
}
__device__ __forceinline__ void mma_bf16(float* c, const uint32_t* a, uint32_t b0, uint32_t b1) {
    asm volatile(
        "mma.sync.aligned.m16n8k16.row.col.f32.bf16.bf16.f32 "
        "{%0,%1,%2,%3}, {%4,%5,%6,%7}, {%8,%9}, {%0,%1,%2,%3};"
        : "+f"(c[0]), "+f"(c[1]), "+f"(c[2]), "+f"(c[3])
        : "r"(a[0]), "r"(a[1]), "r"(a[2]), "r"(a[3]), "r"(b0), "r"(b1));
}

// ---------------- graph preprocessing --------------------------------------
__global__ void zero_deg_kernel() {
    int i = blockIdx.x * blockDim.x + threadIdx.x;
    if (i < NN) g_deg[i] = 0;
}
__global__ void count_deg_kernel(const int* __restrict__ rowE) {
    int e = blockIdx.x * blockDim.x + threadIdx.x;
    if (e < NE) atomicAdd(&g_deg[rowE[e]], 1);
}
__global__ void scan1_kernel() {
    __shared__ int sm[1024];
    int tid = threadIdx.x;
    int i = blockIdx.x * 1024 + tid;
    int v = (i < NN) ? g_deg[i] : 0;
    int x = v;
    sm[tid] = x;
    __syncthreads();
    #pragma unroll
    for (int off = 1; off < 1024; off <<= 1) {
        int t = (tid >= off) ? sm[tid - off] : 0;
        __syncthreads();
        x += t;
        sm[tid] = x;
        __syncthreads();
    }
    if (i < NN) g_rowptr[i] = x - v;
    if (tid == 1023) g_bsum[blockIdx.x] = x;
}
__global__ void scan2_kernel() {
    __shared__ int sm[128];
    int tid = threadIdx.x;
    int v = (tid < SCAN_BLOCKS) ? g_bsum[tid] : 0;
    int x = v;
    sm[tid] = x;
    __syncthreads();
    #pragma unroll
    for (int off = 1; off < 128; off <<= 1) {
        int t = (tid >= off) ? sm[tid - off] : 0;
        __syncthreads();
        x += t;
        sm[tid] = x;
        __syncthreads();
    }
    if (tid < SCAN_BLOCKS) g_bsum[tid] = x - v;
    if (tid == 127) g_rowptr[NN] = x;
}
__global__ void scan3_kernel() {
    int i = blockIdx.x * blockDim.x + threadIdx.x;
    if (i >= NN) return;
    int rp = g_rowptr[i] + g_bsum[i >> 10];
    g_rowptr[i] = rp;
    g_cursor[i] = rp;
    g_dinv[i] = rsqrtf((float)(g_deg[i] + 1));
}
__global__ void fill_csr_kernel(const int* __restrict__ rowE, const int* __restrict__ colE) {
    int e = blockIdx.x * blockDim.x + threadIdx.x;
    if (e >= NE) return;
    int p = atomicAdd(&g_cursor[rowE[e]], 1);
    g_col[p] = colE[e];
}

// ---------------- weight split/transpose: [K][N] fp32 -> [N][K] bf16 hi/lo --
__global__ void convert_w_kernel(const float* __restrict__ W,
                                 __nv_bfloat16* __restrict__ hi,
                                 __nv_bfloat16* __restrict__ lo, int K, int N) {
    int i = blockIdx.x * 256 + threadIdx.x;
    if (i >= K * N) return;
    int n = i / K, k = i % K;
    float v = W[(size_t)k * N + n];
    __nv_bfloat16 h = __float2bfloat16(v);
    hi[i] = h;
    lo[i] = __float2bfloat16(v - __bfloat162float(h));
}

// ---------------- pre-scale x by dinv (layer-0 aggregate-first) -------------
__global__ void scale_x_kernel(const float* __restrict__ x, float* __restrict__ xs) {
    int i = blockIdx.x * 256 + threadIdx.x;
    if (i >= NN * (D_INF / 4)) return;
    int row = i / (D_INF / 4);
    float d = g_dinv[row];
    float4 v = reinterpret_cast<const float4*>(x)[i];
    v.x *= d; v.y *= d; v.z *= d; v.w *= d;
    reinterpret_cast<float4*>(xs)[i] = v;
}

// ---------------- warp-MMA split-bf16 GEMM ----------------------------------
// C[128 x 128-tile] = f(A)[128 x KTOT] @ Wt[colBase..+128, KTOT]^T  (x dinv if SCALE)
// f = BN? relu(bn(.)) : identity.  SMEM: 4 tiles of 128 rows x 64 bf16, SW128.
#define TILE_B 16384
#define GEMM_MMA_SMEM (4 * TILE_B)

template <int KTOT, bool BN, bool SCALE>
__global__ __launch_bounds__(256)
void gemm_mma_kernel(const float* __restrict__ A,
                     const __nv_bfloat16* __restrict__ Whi,
                     const __nv_bfloat16* __restrict__ Wlo,
                     float* __restrict__ C, int ldc) {
    extern __shared__ __align__(1024) char smem[];
    char* sAhi = smem;
    char* sAlo = smem + TILE_B;
    char* sBhi = smem + 2 * TILE_B;
    char* sBlo = smem + 3 * TILE_B;
    uint32_t sb = smem_u32(smem);
    const uint32_t uAhi = sb, uAlo = sb + TILE_B, uBhi = sb + 2 * TILE_B, uBlo = sb + 3 * TILE_B;

    int tid = threadIdx.x, lane = tid & 31, wid = tid >> 5;
    int wm = wid >> 1, wn = wid & 1;             // 4 x 2 warp grid
    int rowBase = blockIdx.x * 128, colBase = blockIdx.y * 128;

    float acc[2][8][4];
    #pragma unroll
    for (int mi = 0; mi < 2; ++mi)
        #pragma unroll
        for (int ni = 0; ni < 8; ++ni)
            #pragma unroll
            for (int q = 0; q < 4; ++q) acc[mi][ni][q] = 0.f;

    int cg = (tid & 7) * 8;   // k-offset (bf16 elems) within 64-wide chunk
    int rr = tid >> 3;        // 0..31

    constexpr int KCH = KTOT / 64;
    for (int ch = 0; ch < KCH; ++ch) {
        int k0 = ch * 64;
        // --- stage A: fp32 -> (BN/relu) -> bf16 hi/lo ---
        #pragma unroll
        for (int p = 0; p < 4; ++p) {
            int r = rr + p * 32;
            int gr = rowBase + r;
            float v[8];
            if (gr < NN) {
                const float4* ap = reinterpret_cast<const float4*>(A + (size_t)gr * KTOT + k0 + cg);
                float4 x0 = ap[0], x1 = ap[1];
                v[0] = x0.x; v[1] = x0.y; v[2] = x0.z; v[3] = x0.w;
                v[4] = x1.x; v[5] = x1.y; v[6] = x1.z; v[7] = x1.w;
            } else {
                #pragma unroll
                for (int j = 0; j < 8; ++j) v[j] = 0.f;
            }
            if (BN) {
                #pragma unroll
                for (int j = 0; j < 8; ++j) {
                    int c = k0 + cg + j;
                    v[j] = fmaxf(fmaf(v[j], g_scale[c], g_shift[c]), 0.f);
                }
            }
            __nv_bfloat16 hi8[8], lo8[8];
            #pragma unroll
            for (int j = 0; j < 8; ++j) {
                __nv_bfloat16 h = __float2bfloat16(v[j]);
                hi8[j] = h;
                lo8[j] = __float2bfloat16(v[j] - __bfloat162float(h));
            }
            uint32_t off = SW128((uint32_t)(r * 128 + cg * 2));
            *reinterpret_cast<uint4*>(sAhi + off) = *reinterpret_cast<uint4*>(hi8);
            *reinterpret_cast<uint4*>(sAlo + off) = *reinterpret_cast<uint4*>(lo8);
        }
        // --- stage B (W rows colBase..colBase+127, [N][K] layout) ---
        #pragma unroll
        for (int p = 0; p < 4; ++p) {
            int n = rr + p * 32;
            const size_t gof = (size_t)(colBase + n) * KTOT + k0 + cg;
            uint4 vh = *reinterpret_cast<const uint4*>(Whi + gof);
            uint4 vl = *reinterpret_cast<const uint4*>(Wlo + gof);
            uint32_t off = SW128((uint32_t)(n * 128 + cg * 2));
            *reinterpret_cast<uint4*>(sBhi + off) = vh;
            *reinterpret_cast<uint4*>(sBlo + off) = vl;
        }
        __syncthreads();

        // --- compute: 4 k16-steps ---
        #pragma unroll
        for (int ks = 0; ks < 4; ++ks) {
            int kk = ks * 16;
            uint32_t ah[2][4], al[2][4];
            #pragma unroll
            for (int mi = 0; mi < 2; ++mi) {
                int r = wm * 32 + mi * 16 + (lane & 15);
                int c = kk + (lane >> 4) * 8;
                uint32_t off = SW128((uint32_t)(r * 128 + c * 2));
                ldm_x4(ah[mi], uAhi + off);
                ldm_x4(al[mi], uAlo + off);
            }
            #pragma unroll
            for (int ni = 0; ni < 8; ++ni) {
                int n = wn * 64 + ni * 8 + (lane & 7);
                int c = kk + ((lane >> 3) & 1) * 8;
                uint32_t off = SW128((uint32_t)(n * 128 + c * 2));
                uint32_t bh0, bh1, bl0, bl1;
                ldm_x2(bh0, bh1, uBhi + off);
                ldm_x2(bl0, bl1, uBlo + off);
                #pragma unroll
                for (int mi = 0; mi < 2; ++mi) {
                    mma_bf16(acc[mi][ni], ah[mi], bh0, bh1);  // hi*hi
                    mma_bf16(acc[mi][ni], ah[mi], bl0, bl1);  // hi*lo
                    mma_bf16(acc[mi][ni], al[mi], bh0, bh1);  // lo*hi
                }
            }
        }
        __syncthreads();
    }

    // --- epilogue ---
    #pragma unroll
    for (int mi = 0; mi < 2; ++mi) {
        int r0 = rowBase + wm * 32 + mi * 16 + (lane >> 2);
        int r1 = r0 + 8;
        float d0 = 1.f, d1 = 1.f;
        if (SCALE) {
            d0 = (r0 < NN) ? g_dinv[r0] : 0.f;
            d1 = (r1 < NN) ? g_dinv[r1] : 0.f;
        }
        #pragma unroll
        for (int ni = 0; ni < 8; ++ni) {
            int c0 = colBase + wn * 64 + ni * 8 + (lane & 3) * 2;
            if (r0 < NN)
                *reinterpret_cast<float2*>(C + (size_t)r0 * ldc + c0) =
                    make_float2(acc[mi][ni][0] * d0, acc[mi][ni][1] * d0);
            if (r1 < NN)
                *reinterpret_cast<float2*>(C + (size_t)r1 * ldc + c0) =
                    make_float2(acc[mi][ni][2] * d1, acc[mi][ni][3] * d1);
        }
    }
}

// ---------------- SIMT SGEMM (final 256->40), BN fold + dinv ----------------
template <int TK, int TN, bool BN>
__global__ __launch_bounds__(256)
void gemm_scale_kernel(const float* __restrict__ A,
                       const float* __restrict__ W,
                       float* __restrict__ C) {
    __shared__ float As[8][132];
    __shared__ float Bs[8][128];
    int tid = threadIdx.x;
    int rowBase = blockIdx.x * 128;
    int colBase = blockIdx.y * 128;
    int ty = tid >> 4, tx = tid & 15;
    int aRow = tid >> 1;
    int aK = (tid & 1) * 4;
    int bK = tid >> 5;
    int bCol = (tid & 31) * 4;

    float acc[8][8];
    #pragma unroll
    for (int i = 0; i < 8; ++i)
        #pragma unroll
        for (int j = 0; j < 8; ++j) acc[i][j] = 0.f;

    for (int k0 = 0; k0 < TK; k0 += 8) {
        float4 av = make_float4(0.f, 0.f, 0.f, 0.f);
        int gr = rowBase + aRow;
        if (gr < NN)
            av = *reinterpret_cast<const float4*>(A + (size_t)gr * TK + k0 + aK);
        if (BN) {
            int c = k0 + aK;
            av.x = fmaxf(fmaf(av.x, g_scale[c + 0], g_shift[c + 0]), 0.f);
            av.y = fmaxf(fmaf(av.y, g_scale[c + 1], g_shift[c + 1]), 0.f);
            av.z = fmaxf(fmaf(av.z, g_scale[c + 2], g_shift[c + 2]), 0.f);
            av.w = fmaxf(fmaf(av.w, g_scale[c + 3], g_shift[c + 3]), 0.f);
        }
        As[aK + 0][aRow] = av.x;
        As[aK + 1][aRow] = av.y;
        As[aK + 2][aRow] = av.z;
        As[aK + 3][aRow] = av.w;

        float4 bv = make_float4(0.f, 0.f, 0.f, 0.f);
        int gc = colBase + bCol;
        if (gc < TN)
            bv = *reinterpret_cast<const float4*>(W + (size_t)(k0 + bK) * TN + gc);
        *reinterpret_cast<float4*>(&Bs[bK][bCol]) = bv;
        __syncthreads();

        #pragma unroll
        for (int kk = 0; kk < 8; ++kk) {
            float a[8], b[8];
            *reinterpret_cast<float4*>(&a[0]) = *reinterpret_cast<const float4*>(&As[kk][ty * 8]);
            *reinterpret_cast<float4*>(&a[4]) = *reinterpret_cast<const float4*>(&As[kk][ty * 8 + 4]);
            *reinterpret_cast<float4*>(&b[0]) = *reinterpret_cast<const float4*>(&Bs[kk][tx * 8]);
            *reinterpret_cast<float4*>(&b[4]) = *reinterpret_cast<const float4*>(&Bs[kk][tx * 8 + 4]);
            #pragma unroll
            for (int i = 0; i < 8; ++i)
                #pragma unroll
                for (int j = 0; j < 8; ++j)
                    acc[i][j] = fmaf(a[i], b[j], acc[i][j]);
        }
        __syncthreads();
    }

    #pragma unroll
    for (int i = 0; i < 8; ++i) {
        int r = rowBase + ty * 8 + i;
        if (r >= NN) continue;
        float s = g_dinv[r];
        #pragma unroll
        for (int j = 0; j < 8; j += 4) {
            int cc = colBase + tx * 8 + j;
            if (cc < TN) {
                float4 v = make_float4(acc[i][j] * s, acc[i][j + 1] * s,
                                       acc[i][j + 2] * s, acc[i][j + 3] * s);
                *reinterpret_cast<float4*>(C + (size_t)r * TN + cc) = v;
            }
        }
    }
}

// ---------------- SpMM (gather CSR), warp per row ---------------------------
template <int NF4>
__global__ __launch_bounds__(256)
void spmm_kernel(const float* __restrict__ hs, float* __restrict__ out) {
    int warp = threadIdx.x >> 5, lane = threadIdx.x & 31;
    int row = blockIdx.x * 8 + warp;
    if (row >= NN) return;
    constexpr int U = NF4 / 32;
    const float4* h4 = reinterpret_cast<const float4*>(hs);
    size_t rb = (size_t)row * NF4;
    float4 acc[U];
    #pragma unroll
    for (int u = 0; u < U; ++u) acc[u] = h4[rb + u * 32 + lane];
    int s = g_rowptr[row], e = g_rowptr[row + 1];
    for (int i = s; i < e; ++i) {
        size_t cb = (size_t)g_col[i] * NF4;
        #pragma unroll
        for (int u = 0; u < U; ++u) {
            float4 v = h4[cb + u * 32 + lane];
            acc[u].x += v.x; acc[u].y += v.y; acc[u].z += v.z; acc[u].w += v.w;
        }
    }
    float d = g_dinv[row];
    float4* o4 = reinterpret_cast<float4*>(out);
    #pragma unroll
    for (int u = 0; u < U; ++u) {
        acc[u].x *= d; acc[u].y *= d; acc[u].z *= d; acc[u].w *= d;
        o4[rb + u * 32 + lane] = acc[u];
    }
}

// ---------------- BatchNorm stats -------------------------------------------
__global__ void zero_stats_kernel() {
    int c = threadIdx.x;
    g_sum[c] = 0.f;
    g_sumsq[c] = 0.f;
}
__global__ __launch_bounds__(256)
void bn_reduce_kernel(const float* __restrict__ y) {
    int c = threadIdx.x;
    int r0 = blockIdx.x * 128;
    int rend = min(r0 + 128, NN);
    float s = 0.f, ss = 0.f;
    for (int r = r0; r < rend; ++r) {
        float v = y[(size_t)r * D_H + c];
        s += v;
        ss += v * v;
    }
    atomicAdd(&g_sum[c], s);
    atomicAdd(&g_sumsq[c], ss);
}
__global__ void bn_finalize_kernel(const float* __restrict__ gamma,
                                   const float* __restrict__ beta) {
    int c = threadIdx.x;
    float mu = g_sum[c] * (1.f / NN);
    float var = g_sumsq[c] * (1.f / NN) - mu * mu;
    float sc = rsqrtf(var + 1e-5f) * gamma[c];
    g_scale[c] = sc;
    g_shift[c] = beta[c] - mu * sc;
}

// ---------------- final SpMM (D=40) + bias + log_softmax --------------------
__global__ __launch_bounds__(256)
void spmm40_softmax_kernel(const float* __restrict__ hs,
                           const float* __restrict__ bl,
                           float* __restrict__ out) {
    int warp = threadIdx.x >> 5, lane = threadIdx.x & 31;
    int row = blockIdx.x * 8 + warp;
    if (row >= NN) return;
    size_t rbase = (size_t)row * D_O;
    float a0 = hs[rbase + lane];
    float a1 = (lane < 8) ? hs[rbase + 32 + lane] : 0.f;
    int s = g_rowptr[row], e = g_rowptr[row + 1];
    for (int i = s; i < e; ++i) {
        size_t cb = (size_t)g_col[i] * D_O;
        a0 += hs[cb + lane];
        if (lane < 8) a1 += hs[cb + 32 + lane];
    }
    float d = g_dinv[row];
    float v0 = fmaf(a0, d, bl[lane]);
    float v1 = (lane < 8) ? fmaf(a1, d, bl[32 + lane]) : 0.f;

    float m = v0;
    if (lane < 8) m = fmaxf(m, v1);
    #pragma unroll
    for (int off = 16; off > 0; off >>= 1)
        m = fmaxf(m, __shfl_xor_sync(0xffffffffu, m, off));
    float sum = expf(v0 - m) + ((lane < 8) ? expf(v1 - m) : 0.f);
    #pragma unroll
    for (int off = 16; off > 0; off >>= 1)
        sum += __shfl_xor_sync(0xffffffffu, sum, off);
    float lse = logf(sum);
    out[rbase + lane] = v0 - m - lse;
    if (lane < 8) out[rbase + 32 + lane] = v1 - m - lse;
}

// ---------------- launcher ---------------------------------------------------
extern "C" void kernel_launch(void* const* d_in, const int* in_sizes, int n_in,
                              void* d_out, int out_size) {
    const float* x     = (const float*)d_in[0];
    const float* W0    = (const float*)d_in[1];
    const float* Wh    = (const float*)d_in[3];
    const float* gamma = (const float*)d_in[5];
    const float* beta  = (const float*)d_in[6];
    const float* Wl    = (const float*)d_in[7];
    const float* bl    = (const float*)d_in[8];
    const int*   ei    = (const int*)d_in[9];
    const int* rowE = ei;
    const int* colE = ei + NE;
    float* out = (float*)d_out;

    float *pA = nullptr, *pB = nullptr;
    __nv_bfloat16 *w0hi, *w0lo, *whhi, *whlo;
    cudaGetSymbolAddress((void**)&pA, g_bufA);
    cudaGetSymbolAddress((void**)&pB, g_bufB);
    cudaGetSymbolAddress((void**)&w0hi, g_w0hi);
    cudaGetSymbolAddress((void**)&w0lo, g_w0lo);
    cudaGetSymbolAddress((void**)&whhi, g_whhi);
    cudaGetSymbolAddress((void**)&whlo, g_whlo);

    cudaFuncSetAttribute(gemm_mma_kernel<128, false, false>,
                         cudaFuncAttributeMaxDynamicSharedMemorySize, GEMM_MMA_SMEM);
    cudaFuncSetAttribute(gemm_mma_kernel<256, true, true>,
                         cudaFuncAttributeMaxDynamicSharedMemorySize, GEMM_MMA_SMEM);

    const int EB = (NE + 255) / 256;
    const int NBLK = (NN + 255) / 256;
    const int MT = (NN + 127) / 128;  // 782 M-tiles
    dim3 mmaGrid(MT, 2);              // N=256 -> 2 col tiles
    dim3 gemmGrid40(MT, 1);
    int spmmGrid = (NN + 7) / 8;
    int bnRedGrid = (NN + 127) / 128;

    // graph preprocessing
    zero_deg_kernel<<<NBLK, 256>>>();
    count_deg_kernel<<<EB, 256>>>(rowE);
    scan1_kernel<<<SCAN_BLOCKS, 1024>>>();
    scan2_kernel<<<1, 128>>>();
    scan3_kernel<<<NBLK, 256>>>();
    fill_csr_kernel<<<EB, 256>>>(rowE, colE);

    // weight split/transpose
    convert_w_kernel<<<(128 * 256 + 255) / 256, 256>>>(W0, w0hi, w0lo, 128, 256);
    for (int l = 0; l < 3; ++l)
        convert_w_kernel<<<(256 * 256 + 255) / 256, 256>>>(
            Wh + (size_t)l * 256 * 256, whhi + (size_t)l * 256 * 256,
            whlo + (size_t)l * 256 * 256, 256, 256);

    // layer 0: aggregate-first (128-wide), then GEMM (b0 cancels under BN)
    scale_x_kernel<<<(NN * 32 + 255) / 256, 256>>>(x, pB);
    spmm_kernel<32><<<spmmGrid, 256>>>(pB, pA);                     // xagg in pA
    gemm_mma_kernel<128, false, false><<<mmaGrid, 256, GEMM_MMA_SMEM>>>(
        pA, w0hi, w0lo, pB, 256);                                   // h0 in pB
    zero_stats_kernel<<<1, 256>>>();
    bn_reduce_kernel<<<bnRedGrid, 256>>>(pB);
    bn_finalize_kernel<<<1, 256>>>(gamma, beta);

    // hidden layers 1..3: GEMM(BN fold, dinv) -> SpMM -> BN stats
    float* src = pB;
    float* dst = pA;
    for (int l = 0; l < 3; ++l) {
        gemm_mma_kernel<256, true, true><<<mmaGrid, 256, GEMM_MMA_SMEM>>>(
            src, whhi + (size_t)l * 256 * 256, whlo + (size_t)l * 256 * 256, dst, 256);
        spmm_kernel<64><<<spmmGrid, 256>>>(dst, src);
        zero_stats_kernel<<<1, 256>>>();
        bn_reduce_kernel<<<bnRedGrid, 256>>>(src);
        bn_finalize_kernel<<<1, 256>>>(gamma + (size_t)(l + 1) * D_H,
                                       beta + (size_t)(l + 1) * D_H);
    }

    // final layer (BN3 folded into A load) + log_softmax
    gemm_scale_kernel<D_H, D_O, true><<<gemmGrid40, 256>>>(src, Wl, dst);
    spmm40_softmax_kernel<<<spmmGrid, 256>>>(dst, bl, out);
}

// round 5
// speedup vs baseline: 1.8403x; 1.2486x over previous
#include <cuda_runtime.h>
#include <cuda_bf16.h>
#include <math.h>
#include <stdint.h>

#define NN    100000
#define NE    1600000
#define D_INF 128
#define D_H   256
#define D_O   40
#define SCAN_BLOCKS ((NN + 1023) / 1024)

// ---------------- scratch (device globals; no allocation allowed) ----------
__device__ __align__(256) float g_bufA[(size_t)NN * D_H];
__device__ __align__(256) float g_bufB[(size_t)NN * D_H];
__device__ int   g_deg[NN];
__device__ float g_dinv[NN];
__device__ int   g_rowptr[NN + 1];
__device__ int   g_cursor[NN];
__device__ int   g_col[NE];
__device__ int   g_bsum[256];
__device__ float g_sum[D_H];
__device__ float g_sumsq[D_H];
__device__ float g_scale[D_H];
__device__ float g_shift[D_H];
__device__ __align__(256) __nv_bfloat16 g_w0hi[256 * 128];
__device__ __align__(256) __nv_bfloat16 g_w0lo[256 * 128];
__device__ __align__(256) __nv_bfloat16 g_whhi[3 * 256 * 256];
__device__ __align__(256) __nv_bfloat16 g_whlo[3 * 256 * 256];

// ---------------- helpers ----------------------------------------------------
__device__ __forceinline__ uint32_t smem_u32(const void* p) {
    uint32_t a;
    asm("{ .reg .u64 t; cvta.to.shared.u64 t, %1; cvt.u32.u64 %0, t; }" : "=r"(a) : "l"(p));
    return a;
}
#define SW128(o) ((o) ^ (((o) >> 3) & 0x70))

__device__ __forceinline__ void ldm_x4(uint32_t* r, uint32_t addr) {
    asm volatile("ldmatrix.sync.aligned.m8n8.x4.shared.b16 {%0,%1,%2,%3}, [%4];"
                 : "=r"(r[0]), "=r"(r[1]), "=r"(r[2]), "=r"(r[3]) : "r"(addr));
}
__device__ __forceinline__ void mma_bf16(float* c, const uint32_t* a, uint32_t b0, uint32_t b1) {
    asm volatile(
        "mma.sync.aligned.m16n8k16.row.col.f32.bf16.bf16.f32 "
        "{%0,%1,%2,%3}, {%4,%5,%6,%7}, {%8,%9}, {%0,%1,%2,%3};"
        : "+f"(c[0]), "+f"(c[1]), "+f"(c[2]), "+f"(c[3])
        : "r"(a[0]), "r"(a[1]), "r"(a[2]), "r"(a[3]), "r"(b0), "r"(b1));
}
__device__ __forceinline__ void cp16(uint32_t dst, const void* src) {
    asm volatile("cp.async.cg.shared.global [%0], [%1], 16;" :: "r"(dst), "l"(src));
}
#define CP_COMMIT() asm volatile("cp.async.commit_group;" ::: "memory")
#define CP_WAIT0()  asm volatile("cp.async.wait_group 0;" ::: "memory")

// ---------------- graph preprocessing --------------------------------------
__global__ void zero_deg_kernel() {
    int i = blockIdx.x * blockDim.x + threadIdx.x;
    if (i < NN) g_deg[i] = 0;
}
__global__ void count_deg_kernel(const int* __restrict__ rowE) {
    int e = blockIdx.x * blockDim.x + threadIdx.x;
    if (e < NE) atomicAdd(&g_deg[rowE[e]], 1);
}
__global__ void scan1_kernel() {
    __shared__ int sm[1024];
    int tid = threadIdx.x;
    int i = blockIdx.x * 1024 + tid;
    int v = (i < NN) ? g_deg[i] : 0;
    int x = v;
    sm[tid] = x;
    __syncthreads();
    #pragma unroll
    for (int off = 1; off < 1024; off <<= 1) {
        int t = (tid >= off) ? sm[tid - off] : 0;
        __syncthreads();
        x += t;
        sm[tid] = x;
        __syncthreads();
    }
    if (i < NN) g_rowptr[i] = x - v;
    if (tid == 1023) g_bsum[blockIdx.x] = x;
}
__global__ void scan2_kernel() {
    __shared__ int sm[128];
    int tid = threadIdx.x;
    int v = (tid < SCAN_BLOCKS) ? g_bsum[tid] : 0;
    int x = v;
    sm[tid] = x;
    __syncthreads();
    #pragma unroll
    for (int off = 1; off < 128; off <<= 1) {
        int t = (tid >= off) ? sm[tid - off] : 0;
        __syncthreads();
        x += t;
        sm[tid] = x;
        __syncthreads();
    }
    if (tid < SCAN_BLOCKS) g_bsum[tid] = x - v;
    if (tid == 127) g_rowptr[NN] = x;
}
__global__ void scan3_kernel() {
    int i = blockIdx.x * blockDim.x + threadIdx.x;
    if (i >= NN) return;
    int rp = g_rowptr[i] + g_bsum[i >> 10];
    g_rowptr[i] = rp;
    g_cursor[i] = rp;
    g_dinv[i] = rsqrtf((float)(g_deg[i] + 1));
}
__global__ void fill_csr_kernel(const int* __restrict__ rowE, const int* __restrict__ colE) {
    int e = blockIdx.x * blockDim.x + threadIdx.x;
    if (e >= NE) return;
    int p = atomicAdd(&g_cursor[rowE[e]], 1);
    g_col[p] = colE[e];
}

// ---------------- fused weight split/transpose ------------------------------
// W0 [128][256] -> g_w0 [256][128]; Wh [3][256][256] -> g_wh [3][256][256] (T)
__global__ void convert_w_all_kernel(const float* __restrict__ W0,
                                     const float* __restrict__ Wh) {
    int i = blockIdx.x * 256 + threadIdx.x;
    if (i < 32768) {
        int n = i >> 7, k = i & 127;
        float v = W0[k * 256 + n];
        __nv_bfloat16 h = __float2bfloat16(v);
        g_w0hi[i] = h;
        g_w0lo[i] = __float2bfloat16(v - __bfloat162float(h));
    } else if (i < 229376) {
        int j = i - 32768;
        int l = j >> 16, r = j & 65535;
        int n = r >> 8, k = r & 255;
        float v = Wh[l * 65536 + k * 256 + n];
        __nv_bfloat16 h = __float2bfloat16(v);
        g_whhi[j] = h;
        g_whlo[j] = __float2bfloat16(v - __bfloat162float(h));
    }
}

// ---------------- pipelined warp-MMA split-bf16 GEMM ------------------------
// C[128 x 256] = f(A)[128 x KTOT] @ Wt[256 x KTOT]^T  (x dinv if SCALE)
// 512 threads, 2-stage cp.async pipeline, K chunks of 64.
#define STG_BYTES 98304
#define OF_AHI 0
#define OF_ALO 16384
#define OF_BHI 32768
#define OF_BLO 65536
#define GEMM_SMEM (2 * STG_BYTES)

template <int KTOT, bool BN, bool SCALE>
__global__ __launch_bounds__(512)
void gemm_mma_kernel(const float* __restrict__ A,
                     const __nv_bfloat16* __restrict__ Whi,
                     const __nv_bfloat16* __restrict__ Wlo,
                     float* __restrict__ C) {
    extern __shared__ __align__(1024) char smem[];
    uint32_t sb = smem_u32(smem);
    int tid = threadIdx.x, lane = tid & 31, wid = tid >> 5;
    int wm = wid >> 2, wn = wid & 3;          // 4 x 4 warp grid, warp tile 32x64
    int rowBase = blockIdx.x * 128;
    constexpr int KCH = KTOT / 64;

    float acc[2][8][4];
    #pragma unroll
    for (int mi = 0; mi < 2; ++mi)
        #pragma unroll
        for (int ni = 0; ni < 8; ++ni)
            #pragma unroll
            for (int q = 0; q < 4; ++q) acc[mi][ni][q] = 0.f;

    int cg = (tid & 7) * 8;   // k-offset within 64-wide chunk
    int rr = tid >> 3;        // 0..63
    float av[2][8];           // A prefetch registers (2 rows x 8 floats)

    auto ldgA = [&](int ch) {
        int k0 = ch * 64;
        #pragma unroll
        for (int p = 0; p < 2; ++p) {
            int gr = rowBase + rr + p * 64;
            if (gr < NN) {
                const float4* ap = reinterpret_cast<const float4*>(A + (size_t)gr * KTOT + k0 + cg);
                float4 x0 = ap[0], x1 = ap[1];
                av[p][0] = x0.x; av[p][1] = x0.y; av[p][2] = x0.z; av[p][3] = x0.w;
                av[p][4] = x1.x; av[p][5] = x1.y; av[p][6] = x1.z; av[p][7] = x1.w;
            } else {
                #pragma unroll
                for (int j = 0; j < 8; ++j) av[p][j] = 0.f;
            }
        }
    };
    auto cpB = [&](int ch, int s) {
        int k0 = ch * 64;
        uint32_t base = sb + s * STG_BYTES;
        #pragma unroll
        for (int p = 0; p < 4; ++p) {
            int n = rr + p * 64;
            size_t go = (size_t)n * KTOT + k0 + cg;
            uint32_t off = SW128((uint32_t)(n * 128 + cg * 2));
            cp16(base + OF_BHI + off, Whi + go);
            cp16(base + OF_BLO + off, Wlo + go);
        }
    };
    auto stsA = [&](int ch, int s) {
        int k0 = ch * 64;
        char* base = smem + s * STG_BYTES;
        #pragma unroll
        for (int p = 0; p < 2; ++p) {
            float v[8];
            #pragma unroll
            for (int j = 0; j < 8; ++j) v[j] = av[p][j];
            if (BN) {
                #pragma unroll
                for (int j = 0; j < 8; ++j) {
                    int c = k0 + cg + j;
                    v[j] = fmaxf(fmaf(v[j], g_scale[c], g_shift[c]), 0.f);
                }
            }
            __nv_bfloat16 hi8[8], lo8[8];
            #pragma unroll
            for (int j = 0; j < 8; ++j) {
                __nv_bfloat16 h = __float2bfloat16(v[j]);
                hi8[j] = h;
                lo8[j] = __float2bfloat16(v[j] - __bfloat162float(h));
            }
            uint32_t off = SW128((uint32_t)((rr + p * 64) * 128 + cg * 2));
            *reinterpret_cast<uint4*>(base + OF_AHI + off) = *reinterpret_cast<uint4*>(hi8);
            *reinterpret_cast<uint4*>(base + OF_ALO + off) = *reinterpret_cast<uint4*>(lo8);
        }
    };
    auto domma = [&](int s) {
        uint32_t aHi = sb + s * STG_BYTES + OF_AHI;
        uint32_t aLo = sb + s * STG_BYTES + OF_ALO;
        uint32_t bHi = sb + s * STG_BYTES + OF_BHI;
        uint32_t bLo = sb + s * STG_BYTES + OF_BLO;
        #pragma unroll
        for (int ks = 0; ks < 4; ++ks) {
            int kk = ks * 16;
            uint32_t ah[2][4], al[2][4];
            #pragma unroll
            for (int mi = 0; mi < 2; ++mi) {
                int r = wm * 32 + mi * 16 + (lane & 15);
                int c = kk + (lane >> 4) * 8;
                uint32_t off = SW128((uint32_t)(r * 128 + c * 2));
                ldm_x4(ah[mi], aHi + off);
                ldm_x4(al[mi], aLo + off);
            }
            #pragma unroll
            for (int nt = 0; nt < 4; ++nt) {
                int g = lane >> 3;
                int row = wn * 64 + nt * 16 + (g >> 1) * 8 + (lane & 7);
                int c = kk + (g & 1) * 8;
                uint32_t off = SW128((uint32_t)(row * 128 + c * 2));
                uint32_t bh[4], bl_[4];
                ldm_x4(bh, bHi + off);
                ldm_x4(bl_, bLo + off);
                #pragma unroll
                for (int half = 0; half < 2; ++half) {
                    int ni = nt * 2 + half;
                    uint32_t b0h = bh[half * 2], b1h = bh[half * 2 + 1];
                    uint32_t b0l = bl_[half * 2], b1l = bl_[half * 2 + 1];
                    #pragma unroll
                    for (int mi = 0; mi < 2; ++mi) {
                        mma_bf16(acc[mi][ni], ah[mi], b0h, b1h);
                        mma_bf16(acc[mi][ni], ah[mi], b0l, b1l);
                        mma_bf16(acc[mi][ni], al[mi], b0h, b1h);
                    }
                }
            }
        }
    };

    // prologue
    ldgA(0);
    cpB(0, 0);
    CP_COMMIT();
    stsA(0, 0);

    for (int ch = 0; ch < KCH; ++ch) {
        int s = ch & 1;
        CP_WAIT0();
        __syncthreads();
        if (ch + 1 < KCH) {
            ldgA(ch + 1);
            cpB(ch + 1, s ^ 1);
            CP_COMMIT();
        }
        domma(s);
        if (ch + 1 < KCH) stsA(ch + 1, s ^ 1);
    }

    // epilogue
    #pragma unroll
    for (int mi = 0; mi < 2; ++mi) {
        int r0 = rowBase + wm * 32 + mi * 16 + (lane >> 2);
        int r1 = r0 + 8;
        float d0 = 1.f, d1 = 1.f;
        if (SCALE) {
            d0 = (r0 < NN) ? g_dinv[r0] : 0.f;
            d1 = (r1 < NN) ? g_dinv[r1] : 0.f;
        }
        #pragma unroll
        for (int ni = 0; ni < 8; ++ni) {
            int c0 = wn * 64 + ni * 8 + (lane & 3) * 2;
            if (r0 < NN)
                *reinterpret_cast<float2*>(C + (size_t)r0 * 256 + c0) =
                    make_float2(acc[mi][ni][0] * d0, acc[mi][ni][1] * d0);
            if (r1 < NN)
                *reinterpret_cast<float2*>(C + (size_t)r1 * 256 + c0) =
                    make_float2(acc[mi][ni][2] * d1, acc[mi][ni][3] * d1);
        }
    }
}

// ---------------- SIMT SGEMM (final 256->40), BN fold + dinv ----------------
template <int TK, int TN, bool BN>
__global__ __launch_bounds__(256)
void gemm_scale_kernel(const float* __restrict__ A,
                       const float* __restrict__ W,
                       float* __restrict__ C) {
    __shared__ float As[8][132];
    __shared__ float Bs[8][128];
    int tid = threadIdx.x;
    int rowBase = blockIdx.x * 128;
    int colBase = blockIdx.y * 128;
    int ty = tid >> 4, tx = tid & 15;
    int aRow = tid >> 1;
    int aK = (tid & 1) * 4;
    int bK = tid >> 5;
    int bCol = (tid & 31) * 4;

    float acc[8][8];
    #pragma unroll
    for (int i = 0; i < 8; ++i)
        #pragma unroll
        for (int j = 0; j < 8; ++j) acc[i][j] = 0.f;

    for (int k0 = 0; k0 < TK; k0 += 8) {
        float4 av = make_float4(0.f, 0.f, 0.f, 0.f);
        int gr = rowBase + aRow;
        if (gr < NN)
            av = *reinterpret_cast<const float4*>(A + (size_t)gr * TK + k0 + aK);
        if (BN) {
            int c = k0 + aK;
            av.x = fmaxf(fmaf(av.x, g_scale[c + 0], g_shift[c + 0]), 0.f);
            av.y = fmaxf(fmaf(av.y, g_scale[c + 1], g_shift[c + 1]), 0.f);
            av.z = fmaxf(fmaf(av.z, g_scale[c + 2], g_shift[c + 2]), 0.f);
            av.w = fmaxf(fmaf(av.w, g_scale[c + 3], g_shift[c + 3]), 0.f);
        }
        As[aK + 0][aRow] = av.x;
        As[aK + 1][aRow] = av.y;
        As[aK + 2][aRow] = av.z;
        As[aK + 3][aRow] = av.w;

        float4 bv = make_float4(0.f, 0.f, 0.f, 0.f);
        int gc = colBase + bCol;
        if (gc < TN)
            bv = *reinterpret_cast<const float4*>(W + (size_t)(k0 + bK) * TN + gc);
        *reinterpret_cast<float4*>(&Bs[bK][bCol]) = bv;
        __syncthreads();

        #pragma unroll
        for (int kk = 0; kk < 8; ++kk) {
            float a[8], b[8];
            *reinterpret_cast<float4*>(&a[0]) = *reinterpret_cast<const float4*>(&As[kk][ty * 8]);
            *reinterpret_cast<float4*>(&a[4]) = *reinterpret_cast<const float4*>(&As[kk][ty * 8 + 4]);
            *reinterpret_cast<float4*>(&b[0]) = *reinterpret_cast<const float4*>(&Bs[kk][tx * 8]);
            *reinterpret_cast<float4*>(&b[4]) = *reinterpret_cast<const float4*>(&Bs[kk][tx * 8 + 4]);
            #pragma unroll
            for (int i = 0; i < 8; ++i)
                #pragma unroll
                for (int j = 0; j < 8; ++j)
                    acc[i][j] = fmaf(a[i], b[j], acc[i][j]);
        }
        __syncthreads();
    }

    #pragma unroll
    for (int i = 0; i < 8; ++i) {
        int r = rowBase + ty * 8 + i;
        if (r >= NN) continue;
        float s = g_dinv[r];
        #pragma unroll
        for (int j = 0; j < 8; j += 4) {
            int cc = colBase + tx * 8 + j;
            if (cc < TN) {
                float4 v = make_float4(acc[i][j] * s, acc[i][j + 1] * s,
                                       acc[i][j + 2] * s, acc[i][j + 3] * s);
                *reinterpret_cast<float4*>(C + (size_t)r * TN + cc) = v;
            }
        }
    }
}

// ---------------- SpMM: 128 columns per pass, warp per row ------------------
// WEIGHTED: per-edge weight dinv[c] and self weight dinv[row] (layer 0)
// STATS: accumulate BN sum/sumsq for the 128 columns handled in this pass
// S4: row stride in float4 units (32 for D=128, 64 for D=256)
template <bool WEIGHTED, bool STATS, int S4>
__global__ __launch_bounds__(512)
void spmm128_kernel(const float* __restrict__ in, float* __restrict__ out, int co4) {
    __shared__ float ss[16][128];
    __shared__ float sq[16][128];
    int warp = threadIdx.x >> 5, lane = threadIdx.x & 31;
    int row = blockIdx.x * 16 + warp;      // NN % 16 == 0: no guard needed
    const float4* in4 = reinterpret_cast<const float4*>(in);
    size_t rb = (size_t)row * S4 + co4 + lane;
    float4 acc = in4[rb];
    if (WEIGHTED) {
        float w = g_dinv[row];
        acc.x *= w; acc.y *= w; acc.z *= w; acc.w *= w;
    }
    int s = g_rowptr[row], e = g_rowptr[row + 1];
    for (int i = s; i < e; ++i) {
        int c = g_col[i];
        float4 v = in4[(size_t)c * S4 + co4 + lane];
        if (WEIGHTED) {
            float w = g_dinv[c];
            acc.x = fmaf(v.x, w, acc.x); acc.y = fmaf(v.y, w, acc.y);
            acc.z = fmaf(v.z, w, acc.z); acc.w = fmaf(v.w, w, acc.w);
        } else {
            acc.x += v.x; acc.y += v.y; acc.z += v.z; acc.w += v.w;
        }
    }
    float d = g_dinv[row];
    acc.x *= d; acc.y *= d; acc.z *= d; acc.w *= d;
    reinterpret_cast<float4*>(out)[rb] = acc;

    if (STATS) {
        int c4 = lane * 4;
        ss[warp][c4 + 0] = acc.x; ss[warp][c4 + 1] = acc.y;
        ss[warp][c4 + 2] = acc.z; ss[warp][c4 + 3] = acc.w;
        sq[warp][c4 + 0] = acc.x * acc.x; sq[warp][c4 + 1] = acc.y * acc.y;
        sq[warp][c4 + 2] = acc.z * acc.z; sq[warp][c4 + 3] = acc.w * acc.w;
        __syncthreads();
        int t = threadIdx.x;
        if (t < 128) {
            float sm = 0.f;
            #pragma unroll
            for (int w = 0; w < 16; ++w) sm += ss[w][t];
            atomicAdd(&g_sum[co4 * 4 + t], sm);
        } else if (t < 256) {
            int c = t - 128;
            float sm = 0.f;
            #pragma unroll
            for (int w = 0; w < 16; ++w) sm += sq[w][c];
            atomicAdd(&g_sumsq[co4 * 4 + c], sm);
        }
    }
}

// ---------------- BN stats (layer-0 GEMM output only) -----------------------
__global__ __launch_bounds__(256)
void bn_reduce_kernel(const float* __restrict__ y) {
    int c = threadIdx.x;
    int r0 = blockIdx.x * 128;
    int rend = min(r0 + 128, NN);
    float s = 0.f, ss = 0.f;
    for (int r = r0; r < rend; ++r) {
        float v = y[(size_t)r * D_H + c];
        s += v;
        ss += v * v;
    }
    atomicAdd(&g_sum[c], s);
    atomicAdd(&g_sumsq[c], ss);
}
// finalize + reset stats for the next layer (keeps graph replays deterministic)
__global__ void bn_finalize_kernel(const float* __restrict__ gamma,
                                   const float* __restrict__ beta) {
    int c = threadIdx.x;
    float mu = g_sum[c] * (1.f / NN);
    float var = g_sumsq[c] * (1.f / NN) - mu * mu;
    float sc = rsqrtf(var + 1e-5f) * gamma[c];
    g_scale[c] = sc;
    g_shift[c] = beta[c] - mu * sc;
    g_sum[c] = 0.f;
    g_sumsq[c] = 0.f;
}

// ---------------- final SpMM (D=40) + bias + log_softmax --------------------
__global__ __launch_bounds__(256)
void spmm40_softmax_kernel(const float* __restrict__ hs,
                           const float* __restrict__ bl,
                           float* __restrict__ out) {
    int warp = threadIdx.x >> 5, lane = threadIdx.x & 31;
    int row = blockIdx.x * 8 + warp;
    if (row >= NN) return;
    size_t rbase = (size_t)row * D_O;
    float a0 = hs[rbase + lane];
    float a1 = (lane < 8) ? hs[rbase + 32 + lane] : 0.f;
    int s = g_rowptr[row], e = g_rowptr[row + 1];
    for (int i = s; i < e; ++i) {
        size_t cb = (size_t)g_col[i] * D_O;
        a0 += hs[cb + lane];
        if (lane < 8) a1 += hs[cb + 32 + lane];
    }
    float d = g_dinv[row];
    float v0 = fmaf(a0, d, bl[lane]);
    float v1 = (lane < 8) ? fmaf(a1, d, bl[32 + lane]) : 0.f;

    float m = v0;
    if (lane < 8) m = fmaxf(m, v1);
    #pragma unroll
    for (int off = 16; off > 0; off >>= 1)
        m = fmaxf(m, __shfl_xor_sync(0xffffffffu, m, off));
    float sum = expf(v0 - m) + ((lane < 8) ? expf(v1 - m) : 0.f);
    #pragma unroll
    for (int off = 16; off > 0; off >>= 1)
        sum += __shfl_xor_sync(0xffffffffu, sum, off);
    float lse = logf(sum);
    out[rbase + lane] = v0 - m - lse;
    if (lane < 8) out[rbase + 32 + lane] = v1 - m - lse;
}

// ---------------- launcher ---------------------------------------------------
extern "C" void kernel_launch(void* const* d_in, const int* in_sizes, int n_in,
                              void* d_out, int out_size) {
    const float* x     = (const float*)d_in[0];
    const float* W0    = (const float*)d_in[1];
    const float* Wh    = (const float*)d_in[3];
    const float* gamma = (const float*)d_in[5];
    const float* beta  = (const float*)d_in[6];
    const float* Wl    = (const float*)d_in[7];
    const float* bl    = (const float*)d_in[8];
    const int*   ei    = (const int*)d_in[9];
    const int* rowE = ei;
    const int* colE = ei + NE;
    float* out = (float*)d_out;

    float *pA = nullptr, *pB = nullptr;
    __nv_bfloat16 *w0hi, *w0lo, *whhi, *whlo;
    cudaGetSymbolAddress((void**)&pA, g_bufA);
    cudaGetSymbolAddress((void**)&pB, g_bufB);
    cudaGetSymbolAddress((void**)&w0hi, g_w0hi);
    cudaGetSymbolAddress((void**)&w0lo, g_w0lo);
    cudaGetSymbolAddress((void**)&whhi, g_whhi);
    cudaGetSymbolAddress((void**)&whlo, g_whlo);

    cudaFuncSetAttribute(gemm_mma_kernel<128, false, false>,
                         cudaFuncAttributeMaxDynamicSharedMemorySize, GEMM_SMEM);
    cudaFuncSetAttribute(gemm_mma_kernel<256, true, true>,
                         cudaFuncAttributeMaxDynamicSharedMemorySize, GEMM_SMEM);

    const int EB = (NE + 255) / 256;
    const int NBLK = (NN + 255) / 256;
    const int MT = (NN + 127) / 128;   // 782 GEMM M-tiles
    const int SPB = NN / 16;           // 6250 spmm blocks (exact)

    // graph preprocessing + weight conversion
    convert_w_all_kernel<<<(229376 + 255) / 256, 256>>>(W0, Wh);
    zero_deg_kernel<<<NBLK, 256>>>();
    count_deg_kernel<<<EB, 256>>>(rowE);
    scan1_kernel<<<SCAN_BLOCKS, 1024>>>();
    scan2_kernel<<<1, 128>>>();
    scan3_kernel<<<NBLK, 256>>>();
    fill_csr_kernel<<<EB, 256>>>(rowE, colE);

    // layer 0: aggregate-first (fused dinv weighting), then tensor GEMM
    spmm128_kernel<true, false, 32><<<SPB, 512>>>(x, pA, 0);   // xagg in pA
    gemm_mma_kernel<128, false, false><<<MT, 512, GEMM_SMEM>>>(pA, w0hi, w0lo, pB);
    bn_reduce_kernel<<<MT, 256>>>(pB);
    bn_finalize_kernel<<<1, 256>>>(gamma, beta);

    // hidden layers 1..3: GEMM(BN fold, dinv) -> column-split SpMM (+stats)
    for (int l = 0; l < 3; ++l) {
        gemm_mma_kernel<256, true, true><<<MT, 512, GEMM_SMEM>>>(
            pB, whhi + (size_t)l * 65536, whlo + (size_t)l * 65536, pA);
        spmm128_kernel<false, true, 64><<<SPB, 512>>>(pA, pB, 0);
        spmm128_kernel<false, true, 64><<<SPB, 512>>>(pA, pB, 32);
        bn_finalize_kernel<<<1, 256>>>(gamma + (size_t)(l + 1) * D_H,
                                       beta + (size_t)(l + 1) * D_H);
    }

    // final layer (BN3 folded into A load) + log_softmax
    dim3 gemmGrid40(MT, 1);
    gemm_scale_kernel<D_H, D_O, true><<<gemmGrid40, 256>>>(pB, Wl, pA);
    spmm40_softmax_kernel<<<NN / 8, 256>>>(pA, bl, out);
}

// round 6
// speedup vs baseline: 2.0637x; 1.1214x over previous
#include <cuda_runtime.h>
#include <cuda_bf16.h>
#include <math.h>
#include <stdint.h>

#define NN    100000
#define NE    1600000
#define D_INF 128
#define D_H   256
#define D_O   40
#define SCAN_BLOCKS ((NN + 1023) / 1024)

// ---------------- scratch (device globals; no allocation allowed) ----------
__device__ __align__(256) float g_bufA[(size_t)NN * D_H];
__device__ __align__(256) float g_bufB[(size_t)NN * D_H];
__device__ int   g_deg[NN];
__device__ float g_dinv[NN];
__device__ int   g_rowptr[NN + 1];
__device__ int   g_cursor[NN];
__device__ int   g_col[NE];
__device__ int   g_bsum[256];
__device__ float g_sum[D_H];
__device__ float g_sumsq[D_H];
__device__ float g_scale[D_H];
__device__ float g_shift[D_H];
__device__ __align__(256) __nv_bfloat16 g_w0hi[256 * 128];
__device__ __align__(256) __nv_bfloat16 g_w0lo[256 * 128];
__device__ __align__(256) __nv_bfloat16 g_whhi[3 * 256 * 256];
__device__ __align__(256) __nv_bfloat16 g_whlo[3 * 256 * 256];
__device__ __align__(256) __nv_bfloat16 g_wlhi[64 * 256];
__device__ __align__(256) __nv_bfloat16 g_wllo[64 * 256];

// ---------------- helpers ----------------------------------------------------
__device__ __forceinline__ uint32_t smem_u32(const void* p) {
    uint32_t a;
    asm("{ .reg .u64 t; cvta.to.shared.u64 t, %1; cvt.u32.u64 %0, t; }" : "=r"(a) : "l"(p));
    return a;
}
#define SW128(o) ((o) ^ (((o) >> 3) & 0x70))

__device__ __forceinline__ void ldm_x4(uint32_t* r, uint32_t addr) {
    asm volatile("ldmatrix.sync.aligned.m8n8.x4.shared.b16 {%0,%1,%2,%3}, [%4];"
                 : "=r"(r[0]), "=r"(r[1]), "=r"(r[2]), "=r"(r[3]) : "r"(addr));
}
__device__ __forceinline__ void mma_bf16(float* c, const uint32_t* a, uint32_t b0, uint32_t b1) {
    asm volatile(
        "mma.sync.aligned.m16n8k16.row.col.f32.bf16.bf16.f32 "
        "{%0,%1,%2,%3}, {%4,%5,%6,%7}, {%8,%9}, {%0,%1,%2,%3};"
        : "+f"(c[0]), "+f"(c[1]), "+f"(c[2]), "+f"(c[3])
        : "r"(a[0]), "r"(a[1]), "r"(a[2]), "r"(a[3]), "r"(b0), "r"(b1));
}
__device__ __forceinline__ void cp16(uint32_t dst, const void* src) {
    asm volatile("cp.async.cg.shared.global [%0], [%1], 16;" :: "r"(dst), "l"(src));
}
#define CP_COMMIT() asm volatile("cp.async.commit_group;" ::: "memory")
#define CP_WAIT0()  asm volatile("cp.async.wait_group 0;" ::: "memory")

// ---------------- graph preprocessing --------------------------------------
__global__ void count_deg_kernel(const int* __restrict__ rowE) {
    int e = blockIdx.x * blockDim.x + threadIdx.x;
    if (e < NE) atomicAdd(&g_deg[rowE[e]], 1);
}
__global__ void scan1_kernel() {
    __shared__ int sm[1024];
    int tid = threadIdx.x;
    int i = blockIdx.x * 1024 + tid;
    int v = (i < NN) ? g_deg[i] : 0;
    int x = v;
    sm[tid] = x;
    __syncthreads();
    #pragma unroll
    for (int off = 1; off < 1024; off <<= 1) {
        int t = (tid >= off) ? sm[tid - off] : 0;
        __syncthreads();
        x += t;
        sm[tid] = x;
        __syncthreads();
    }
    if (i < NN) g_rowptr[i] = x - v;
    if (tid == 1023) g_bsum[blockIdx.x] = x;
}
__global__ void scan2_kernel() {
    __shared__ int sm[128];
    int tid = threadIdx.x;
    int v = (tid < SCAN_BLOCKS) ? g_bsum[tid] : 0;
    int x = v;
    sm[tid] = x;
    __syncthreads();
    #pragma unroll
    for (int off = 1; off < 128; off <<= 1) {
        int t = (tid >= off) ? sm[tid - off] : 0;
        __syncthreads();
        x += t;
        sm[tid] = x;
        __syncthreads();
    }
    if (tid < SCAN_BLOCKS) g_bsum[tid] = x - v;
    if (tid == 127) g_rowptr[NN] = x;
}
__global__ void scan3_kernel() {
    int i = blockIdx.x * blockDim.x + threadIdx.x;
    if (i >= NN) return;
    int rp = g_rowptr[i] + g_bsum[i >> 10];
    g_rowptr[i] = rp;
    g_cursor[i] = rp;
    g_dinv[i] = rsqrtf((float)(g_deg[i] + 1));
}
__global__ void fill_csr_kernel(const int* __restrict__ rowE, const int* __restrict__ colE) {
    int e = blockIdx.x * blockDim.x + threadIdx.x;
    if (e >= NE) return;
    int p = atomicAdd(&g_cursor[rowE[e]], 1);
    g_col[p] = colE[e];
}

// ---------------- fused prep: zero degrees + split/transpose all weights ----
// W0 [128][256] -> [256][128]; Wh [3][256][256] -> T; Wl [256][40] -> [64][256] padded
#define CVT_TOTAL (32768 + 196608 + 16384)
__global__ void convert_w_all_kernel(const float* __restrict__ W0,
                                     const float* __restrict__ Wh,
                                     const float* __restrict__ Wl) {
    int i = blockIdx.x * 256 + threadIdx.x;
    if (i < NN) g_deg[i] = 0;
    if (i < 32768) {
        int n = i >> 7, k = i & 127;
        float v = W0[k * 256 + n];
        __nv_bfloat16 h = __float2bfloat16(v);
        g_w0hi[i] = h;
        g_w0lo[i] = __float2bfloat16(v - __bfloat162float(h));
    } else if (i < 229376) {
        int j = i - 32768;
        int l = j >> 16, r = j & 65535;
        int n = r >> 8, k = r & 255;
        float v = Wh[l * 65536 + k * 256 + n];
        __nv_bfloat16 h = __float2bfloat16(v);
        g_whhi[j] = h;
        g_whlo[j] = __float2bfloat16(v - __bfloat162float(h));
    } else if (i < CVT_TOTAL) {
        int j = i - 229376;
        int n = j >> 8, k = j & 255;
        float v = (n < D_O) ? Wl[k * D_O + n] : 0.f;
        __nv_bfloat16 h = __float2bfloat16(v);
        g_wlhi[j] = h;
        g_wllo[j] = __float2bfloat16(v - __bfloat162float(h));
    }
}

// ---------------- pipelined warp-MMA split-bf16 GEMM ------------------------
// C[128 x NT] = f(A)[128 x KTOT] @ Wt[NT x KTOT]^T  (x dinv if SCALE)
// 512 threads, 16 warps (4x4), warp tile 32 x (NT/4). 2-stage cp.async pipe.
#define OF_ALO 16384
#define OF_BHI 32768

template <int KTOT, int NT, bool BN, bool SCALE, bool STATS>
__global__ __launch_bounds__(512)
void gemm_mma_kernel(const float* __restrict__ A,
                     const __nv_bfloat16* __restrict__ Whi,
                     const __nv_bfloat16* __restrict__ Wlo,
                     float* __restrict__ C) {
    constexpr int STG = 32768 + 2 * NT * 128;   // A(hi+lo) + B(hi+lo) per stage
    constexpr int OF_BLO = 32768 + NT * 128;
    constexpr int NPW = NT / 4;                 // cols per warp
    constexpr int NI = NPW / 8;                 // 8x-col fragments per warp
    constexpr int KCH = KTOT / 64;

    extern __shared__ __align__(1024) char smem[];
    uint32_t sb = smem_u32(smem);
    int tid = threadIdx.x, lane = tid & 31, wid = tid >> 5;
    int wm = wid >> 2, wn = wid & 3;
    int rowBase = blockIdx.x * 128;

    float acc[2][NI][4];
    #pragma unroll
    for (int mi = 0; mi < 2; ++mi)
        #pragma unroll
        for (int ni = 0; ni < NI; ++ni)
            #pragma unroll
            for (int q = 0; q < 4; ++q) acc[mi][ni][q] = 0.f;

    int cg = (tid & 7) * 8;
    int rr = tid >> 3;
    float av[2][8];

    auto ldgA = [&](int ch) {
        int k0 = ch * 64;
        #pragma unroll
        for (int p = 0; p < 2; ++p) {
            int gr = rowBase + rr + p * 64;
            if (gr < NN) {
                const float4* ap = reinterpret_cast<const float4*>(A + (size_t)gr * KTOT + k0 + cg);
                float4 x0 = ap[0], x1 = ap[1];
                av[p][0] = x0.x; av[p][1] = x0.y; av[p][2] = x0.z; av[p][3] = x0.w;
                av[p][4] = x1.x; av[p][5] = x1.y; av[p][6] = x1.z; av[p][7] = x1.w;
            } else {
                #pragma unroll
                for (int j = 0; j < 8; ++j) av[p][j] = 0.f;
            }
        }
    };
    auto cpB = [&](int ch, int s) {
        int k0 = ch * 64;
        uint32_t base = sb + s * STG;
        #pragma unroll
        for (int p = 0; p < NT / 64; ++p) {
            int n = rr + p * 64;
            size_t go = (size_t)n * KTOT + k0 + cg;
            uint32_t off = SW128((uint32_t)(n * 128 + cg * 2));
            cp16(base + OF_BHI + off, Whi + go);
            cp16(base + OF_BLO + off, Wlo + go);
        }
    };
    auto stsA = [&](int ch, int s) {
        int k0 = ch * 64;
        char* base = smem + s * STG;
        #pragma unroll
        for (int p = 0; p < 2; ++p) {
            float v[8];
            #pragma unroll
            for (int j = 0; j < 8; ++j) v[j] = av[p][j];
            if (BN) {
                #pragma unroll
                for (int j = 0; j < 8; ++j) {
                    int c = k0 + cg + j;
                    v[j] = fmaxf(fmaf(v[j], g_scale[c], g_shift[c]), 0.f);
                }
            }
            __nv_bfloat16 hi8[8], lo8[8];
            #pragma unroll
            for (int j = 0; j < 8; ++j) {
                __nv_bfloat16 h = __float2bfloat16(v[j]);
                hi8[j] = h;
                lo8[j] = __float2bfloat16(v[j] - __bfloat162float(h));
            }
            uint32_t off = SW128((uint32_t)((rr + p * 64) * 128 + cg * 2));
            *reinterpret_cast<uint4*>(base + off) = *reinterpret_cast<uint4*>(hi8);
            *reinterpret_cast<uint4*>(base + OF_ALO + off) = *reinterpret_cast<uint4*>(lo8);
        }
    };
    auto domma = [&](int s) {
        uint32_t aHi = sb + s * STG;
        uint32_t aLo = aHi + OF_ALO;
        uint32_t bHi = aHi + OF_BHI;
        uint32_t bLo = aHi + OF_BLO;
        #pragma unroll
        for (int ks = 0; ks < 4; ++ks) {
            int kk = ks * 16;
            uint32_t ah[2][4], al[2][4];
            #pragma unroll
            for (int mi = 0; mi < 2; ++mi) {
                int r = wm * 32 + mi * 16 + (lane & 15);
                int c = kk + (lane >> 4) * 8;
                uint32_t off = SW128((uint32_t)(r * 128 + c * 2));
                ldm_x4(ah[mi], aHi + off);
                ldm_x4(al[mi], aLo + off);
            }
            #pragma unroll
            for (int nt = 0; nt < NI / 2; ++nt) {
                int g = lane >> 3;
                int row = wn * NPW + nt * 16 + (g >> 1) * 8 + (lane & 7);
                int c = kk + (g & 1) * 8;
                uint32_t off = SW128((uint32_t)(row * 128 + c * 2));
                uint32_t bh[4], bl_[4];
                ldm_x4(bh, bHi + off);
                ldm_x4(bl_, bLo + off);
                #pragma unroll
                for (int half = 0; half < 2; ++half) {
                    int ni = nt * 2 + half;
                    uint32_t b0h = bh[half * 2], b1h = bh[half * 2 + 1];
                    uint32_t b0l = bl_[half * 2], b1l = bl_[half * 2 + 1];
                    #pragma unroll
                    for (int mi = 0; mi < 2; ++mi) {
                        mma_bf16(acc[mi][ni], ah[mi], b0h, b1h);
                        mma_bf16(acc[mi][ni], ah[mi], b0l, b1l);
                        mma_bf16(acc[mi][ni], al[mi], b0h, b1h);
                    }
                }
            }
        }
    };

    ldgA(0);
    cpB(0, 0);
    CP_COMMIT();
    stsA(0, 0);

    for (int ch = 0; ch < KCH; ++ch) {
        int s = ch & 1;
        CP_WAIT0();
        __syncthreads();
        if (ch + 1 < KCH) {
            ldgA(ch + 1);
            cpB(ch + 1, s ^ 1);
            CP_COMMIT();
        }
        domma(s);
        if (ch + 1 < KCH) stsA(ch + 1, s ^ 1);
    }

    // epilogue: store (x dinv if SCALE)
    #pragma unroll
    for (int mi = 0; mi < 2; ++mi) {
        int r0 = rowBase + wm * 32 + mi * 16 + (lane >> 2);
        int r1 = r0 + 8;
        float d0 = 1.f, d1 = 1.f;
        if (SCALE) {
            d0 = (r0 < NN) ? g_dinv[r0] : 0.f;
            d1 = (r1 < NN) ? g_dinv[r1] : 0.f;
        }
        #pragma unroll
        for (int ni = 0; ni < NI; ++ni) {
            int c0 = wn * NPW + ni * 8 + (lane & 3) * 2;
            if (r0 < NN)
                *reinterpret_cast<float2*>(C + (size_t)r0 * NT + c0) =
                    make_float2(acc[mi][ni][0] * d0, acc[mi][ni][1] * d0);
            if (r1 < NN)
                *reinterpret_cast<float2*>(C + (size_t)r1 * NT + c0) =
                    make_float2(acc[mi][ni][2] * d1, acc[mi][ni][3] * d1);
        }
    }

    // fused BN stats (layer-0 GEMM): padding rows contribute exact zeros
    if constexpr (STATS) {
        __shared__ float s_sum[256];
        __shared__ float s_sq[256];
        if (tid < 256) { s_sum[tid] = 0.f; s_sq[tid] = 0.f; }
        __syncthreads();
        #pragma unroll
        for (int ni = 0; ni < NI; ++ni) {
            float s0 = 0.f, q0 = 0.f, s1 = 0.f, q1 = 0.f;
            #pragma unroll
            for (int mi = 0; mi < 2; ++mi) {
                float va = acc[mi][ni][0], vb = acc[mi][ni][2];
                s0 += va + vb; q0 += va * va + vb * vb;
                float vc = acc[mi][ni][1], vd = acc[mi][ni][3];
                s1 += vc + vd; q1 += vc * vc + vd * vd;
            }
            #pragma unroll
            for (int off = 4; off <= 16; off <<= 1) {
                s0 += __shfl_xor_sync(0xffffffffu, s0, off);
                q0 += __shfl_xor_sync(0xffffffffu, q0, off);
                s1 += __shfl_xor_sync(0xffffffffu, s1, off);
                q1 += __shfl_xor_sync(0xffffffffu, q1, off);
            }
            if ((lane >> 2) == 0) {
                int c0 = wn * NPW + ni * 8 + (lane & 3) * 2;
                atomicAdd(&s_sum[c0], s0);
                atomicAdd(&s_sq[c0], q0);
                atomicAdd(&s_sum[c0 + 1], s1);
                atomicAdd(&s_sq[c0 + 1], q1);
            }
        }
        __syncthreads();
        if (tid < 256) {
            atomicAdd(&g_sum[tid], s_sum[tid]);
            atomicAdd(&g_sumsq[tid], s_sq[tid]);
        }
    }
}

// ---------------- SpMM: 128 columns per pass, warp per row ------------------
template <bool WEIGHTED, bool STATS, int S4>
__global__ __launch_bounds__(512)
void spmm128_kernel(const float* __restrict__ in, float* __restrict__ out, int co4) {
    __shared__ float ss[16][128];
    __shared__ float sq[16][128];
    int warp = threadIdx.x >> 5, lane = threadIdx.x & 31;
    int row = blockIdx.x * 16 + warp;
    const float4* in4 = reinterpret_cast<const float4*>(in);
    size_t rb = (size_t)row * S4 + co4 + lane;
    float4 acc = in4[rb];
    if (WEIGHTED) {
        float w = g_dinv[row];
        acc.x *= w; acc.y *= w; acc.z *= w; acc.w *= w;
    }
    int s = g_rowptr[row], e = g_rowptr[row + 1];
    for (int i = s; i < e; ++i) {
        int c = g_col[i];
        float4 v = in4[(size_t)c * S4 + co4 + lane];
        if (WEIGHTED) {
            float w = g_dinv[c];
            acc.x = fmaf(v.x, w, acc.x); acc.y = fmaf(v.y, w, acc.y);
            acc.z = fmaf(v.z, w, acc.z); acc.w = fmaf(v.w, w, acc.w);
        } else {
            acc.x += v.x; acc.y += v.y; acc.z += v.z; acc.w += v.w;
        }
    }
    float d = g_dinv[row];
    acc.x *= d; acc.y *= d; acc.z *= d; acc.w *= d;
    reinterpret_cast<float4*>(out)[rb] = acc;

    if (STATS) {
        int c4 = lane * 4;
        ss[warp][c4 + 0] = acc.x; ss[warp][c4 + 1] = acc.y;
        ss[warp][c4 + 2] = acc.z; ss[warp][c4 + 3] = acc.w;
        sq[warp][c4 + 0] = acc.x * acc.x; sq[warp][c4 + 1] = acc.y * acc.y;
        sq[warp][c4 + 2] = acc.z * acc.z; sq[warp][c4 + 3] = acc.w * acc.w;
        __syncthreads();
        int t = threadIdx.x;
        if (t < 128) {
            float sm = 0.f;
            #pragma unroll
            for (int w = 0; w < 16; ++w) sm += ss[w][t];
            atomicAdd(&g_sum[co4 * 4 + t], sm);
        } else if (t < 256) {
            int c = t - 128;
            float sm = 0.f;
            #pragma unroll
            for (int w = 0; w < 16; ++w) sm += sq[w][c];
            atomicAdd(&g_sumsq[co4 * 4 + c], sm);
        }
    }
}

// ---------------- BN finalize (+reset stats for graph-replay determinism) ---
__global__ void bn_finalize_kernel(const float* __restrict__ gamma,
                                   const float* __restrict__ beta) {
    int c = threadIdx.x;
    float mu = g_sum[c] * (1.f / NN);
    float var = g_sumsq[c] * (1.f / NN) - mu * mu;
    float sc = rsqrtf(var + 1e-5f) * gamma[c];
    g_scale[c] = sc;
    g_shift[c] = beta[c] - mu * sc;
    g_sum[c] = 0.f;
    g_sumsq[c] = 0.f;
}

// ---------------- final SpMM (64-stride in, 40 cols) + bias + log_softmax ---
__global__ __launch_bounds__(256)
void spmm40_softmax_kernel(const float* __restrict__ hs,
                           const float* __restrict__ bl,
                           float* __restrict__ out) {
    int warp = threadIdx.x >> 5, lane = threadIdx.x & 31;
    int row = blockIdx.x * 8 + warp;
    if (row >= NN) return;
    size_t rbase = (size_t)row * 64;
    float a0 = hs[rbase + lane];
    float a1 = (lane < 8) ? hs[rbase + 32 + lane] : 0.f;
    int s = g_rowptr[row], e = g_rowptr[row + 1];
    for (int i = s; i < e; ++i) {
        size_t cb = (size_t)g_col[i] * 64;
        a0 += hs[cb + lane];
        if (lane < 8) a1 += hs[cb + 32 + lane];
    }
    float d = g_dinv[row];
    float v0 = fmaf(a0, d, bl[lane]);
    float v1 = (lane < 8) ? fmaf(a1, d, bl[32 + lane]) : 0.f;

    float m = v0;
    if (lane < 8) m = fmaxf(m, v1);
    #pragma unroll
    for (int off = 16; off > 0; off >>= 1)
        m = fmaxf(m, __shfl_xor_sync(0xffffffffu, m, off));
    float sum = expf(v0 - m) + ((lane < 8) ? expf(v1 - m) : 0.f);
    #pragma unroll
    for (int off = 16; off > 0; off >>= 1)
        sum += __shfl_xor_sync(0xffffffffu, sum, off);
    float lse = logf(sum);
    size_t ob = (size_t)row * D_O;
    out[ob + lane] = v0 - m - lse;
    if (lane < 8) out[ob + 32 + lane] = v1 - m - lse;
}

// ---------------- launcher ---------------------------------------------------
extern "C" void kernel_launch(void* const* d_in, const int* in_sizes, int n_in,
                              void* d_out, int out_size) {
    const float* x     = (const float*)d_in[0];
    const float* W0    = (const float*)d_in[1];
    const float* Wh    = (const float*)d_in[3];
    const float* gamma = (const float*)d_in[5];
    const float* beta  = (const float*)d_in[6];
    const float* Wl    = (const float*)d_in[7];
    const float* bl    = (const float*)d_in[8];
    const int*   ei    = (const int*)d_in[9];
    const int* rowE = ei;
    const int* colE = ei + NE;
    float* out = (float*)d_out;

    float *pA = nullptr, *pB = nullptr;
    __nv_bfloat16 *w0hi, *w0lo, *whhi, *whlo, *wlhi, *wllo;
    cudaGetSymbolAddress((void**)&pA, g_bufA);
    cudaGetSymbolAddress((void**)&pB, g_bufB);
    cudaGetSymbolAddress((void**)&w0hi, g_w0hi);
    cudaGetSymbolAddress((void**)&w0lo, g_w0lo);
    cudaGetSymbolAddress((void**)&whhi, g_whhi);
    cudaGetSymbolAddress((void**)&whlo, g_whlo);
    cudaGetSymbolAddress((void**)&wlhi, g_wlhi);
    cudaGetSymbolAddress((void**)&wllo, g_wllo);

    constexpr int SMEM256 = 2 * (32768 + 2 * 256 * 128);  // 196608
    constexpr int SMEM64  = 2 * (32768 + 2 * 64 * 128);   //  98304
    cudaFuncSetAttribute(gemm_mma_kernel<128, 256, false, false, true>,
                         cudaFuncAttributeMaxDynamicSharedMemorySize, SMEM256);
    cudaFuncSetAttribute(gemm_mma_kernel<256, 256, true, true, false>,
                         cudaFuncAttributeMaxDynamicSharedMemorySize, SMEM256);
    cudaFuncSetAttribute(gemm_mma_kernel<256, 64, true, true, false>,
                         cudaFuncAttributeMaxDynamicSharedMemorySize, SMEM64);

    const int EB = (NE + 255) / 256;
    const int NBLK = (NN + 255) / 256;
    const int MT = (NN + 127) / 128;
    const int SPB = NN / 16;

    // prep: weights + degree zero (fused), CSR build
    convert_w_all_kernel<<<(CVT_TOTAL + 255) / 256, 256>>>(W0, Wh, Wl);
    count_deg_kernel<<<EB, 256>>>(rowE);
    scan1_kernel<<<SCAN_BLOCKS, 1024>>>();
    scan2_kernel<<<1, 128>>>();
    scan3_kernel<<<NBLK, 256>>>();
    fill_csr_kernel<<<EB, 256>>>(rowE, colE);

    // layer 0: aggregate-first (fused dinv weighting), GEMM with fused BN stats
    spmm128_kernel<true, false, 32><<<SPB, 512>>>(x, pA, 0);
    gemm_mma_kernel<128, 256, false, false, true><<<MT, 512, SMEM256>>>(pA, w0hi, w0lo, pB);
    bn_finalize_kernel<<<1, 256>>>(gamma, beta);

    // hidden layers 1..3
    for (int l = 0; l < 3; ++l) {
        gemm_mma_kernel<256, 256, true, true, false><<<MT, 512, SMEM256>>>(
            pB, whhi + (size_t)l * 65536, whlo + (size_t)l * 65536, pA);
        spmm128_kernel<false, true, 64><<<SPB, 512>>>(pA, pB, 0);
        spmm128_kernel<false, true, 64><<<SPB, 512>>>(pA, pB, 32);
        bn_finalize_kernel<<<1, 256>>>(gamma + (size_t)(l + 1) * D_H,
                                       beta + (size_t)(l + 1) * D_H);
    }

    // final layer: MMA GEMM (N padded to 64, BN3 fold + dinv) + softmax SpMM
    gemm_mma_kernel<256, 64, true, true, false><<<MT, 512, SMEM64>>>(pB, wlhi, wllo, pA);
    spmm40_softmax_kernel<<<NN / 8, 256>>>(pA, bl, out);
}

// round 7
// speedup vs baseline: 2.2412x; 1.0860x over previous
#include <cuda_runtime.h>
#include <cuda_bf16.h>
#include <cuda_fp16.h>
#include <math.h>
#include <stdint.h>

#define NN    100000
#define NE    1600000
#define D_INF 128
#define D_H   256
#define D_O   40
#define SCAN_BLOCKS ((NN + 1023) / 1024)

// ---------------- scratch (device globals; no allocation allowed) ----------
__device__ __align__(256) float  g_bufA[(size_t)NN * D_H];
__device__ __align__(256) float  g_bufB[(size_t)NN * D_H];
__device__ __align__(256) __half g_bufH[(size_t)NN * D_H];   // fp16 SpMM input
__device__ int   g_deg[NN];
__device__ float g_dinv[NN];
__device__ int   g_rowptr[NN + 1];
__device__ int   g_cursor[NN];
__device__ int   g_col[NE];
__device__ int   g_bsum[256];
__device__ float g_sum[D_H];
__device__ float g_sumsq[D_H];
__device__ float g_scale[D_H];
__device__ float g_shift[D_H];
__device__ __align__(256) __nv_bfloat16 g_w0hi[256 * 128];
__device__ __align__(256) __nv_bfloat16 g_w0lo[256 * 128];
__device__ __align__(256) __nv_bfloat16 g_whhi[3 * 256 * 256];
__device__ __align__(256) __nv_bfloat16 g_whlo[3 * 256 * 256];
__device__ __align__(256) __nv_bfloat16 g_wlhi[64 * 256];
__device__ __align__(256) __nv_bfloat16 g_wllo[64 * 256];

// ---------------- helpers ----------------------------------------------------
__device__ __forceinline__ uint32_t smem_u32(const void* p) {
    uint32_t a;
    asm("{ .reg .u64 t; cvta.to.shared.u64 t, %1; cvt.u32.u64 %0, t; }" : "=r"(a) : "l"(p));
    return a;
}
#define SW128(o) ((o) ^ (((o) >> 3) & 0x70))

__device__ __forceinline__ void ldm_x4(uint32_t* r, uint32_t addr) {
    asm volatile("ldmatrix.sync.aligned.m8n8.x4.shared.b16 {%0,%1,%2,%3}, [%4];"
                 : "=r"(r[0]), "=r"(r[1]), "=r"(r[2]), "=r"(r[3]) : "r"(addr));
}
__device__ __forceinline__ void mma_bf16(float* c, const uint32_t* a, uint32_t b0, uint32_t b1) {
    asm volatile(
        "mma.sync.aligned.m16n8k16.row.col.f32.bf16.bf16.f32 "
        "{%0,%1,%2,%3}, {%4,%5,%6,%7}, {%8,%9}, {%0,%1,%2,%3};"
        : "+f"(c[0]), "+f"(c[1]), "+f"(c[2]), "+f"(c[3])
        : "r"(a[0]), "r"(a[1]), "r"(a[2]), "r"(a[3]), "r"(b0), "r"(b1));
}
__device__ __forceinline__ void cp16(uint32_t dst, const void* src) {
    asm volatile("cp.async.cg.shared.global [%0], [%1], 16;" :: "r"(dst), "l"(src));
}
#define CP_COMMIT() asm volatile("cp.async.commit_group;" ::: "memory")
#define CP_WAIT0()  asm volatile("cp.async.wait_group 0;" ::: "memory")

// ---------------- graph preprocessing --------------------------------------
__global__ void count_deg_kernel(const int* __restrict__ rowE) {
    int e = blockIdx.x * blockDim.x + threadIdx.x;
    if (e < NE) atomicAdd(&g_deg[rowE[e]], 1);
}
__global__ void scan1_kernel() {
    __shared__ int sm[1024];
    int tid = threadIdx.x;
    int i = blockIdx.x * 1024 + tid;
    int v = (i < NN) ? g_deg[i] : 0;
    int x = v;
    sm[tid] = x;
    __syncthreads();
    #pragma unroll
    for (int off = 1; off < 1024; off <<= 1) {
        int t = (tid >= off) ? sm[tid - off] : 0;
        __syncthreads();
        x += t;
        sm[tid] = x;
        __syncthreads();
    }
    if (i < NN) g_rowptr[i] = x - v;
    if (tid == 1023) g_bsum[blockIdx.x] = x;
}
__global__ void scan2_kernel() {
    __shared__ int sm[128];
    int tid = threadIdx.x;
    int v = (tid < SCAN_BLOCKS) ? g_bsum[tid] : 0;
    int x = v;
    sm[tid] = x;
    __syncthreads();
    #pragma unroll
    for (int off = 1; off < 128; off <<= 1) {
        int t = (tid >= off) ? sm[tid - off] : 0;
        __syncthreads();
        x += t;
        sm[tid] = x;
        __syncthreads();
    }
    if (tid < SCAN_BLOCKS) g_bsum[tid] = x - v;
    if (tid == 127) g_rowptr[NN] = x;
}
__global__ void scan3_kernel() {
    int i = blockIdx.x * blockDim.x + threadIdx.x;
    if (i >= NN) return;
    int rp = g_rowptr[i] + g_bsum[i >> 10];
    g_rowptr[i] = rp;
    g_cursor[i] = rp;
    g_dinv[i] = rsqrtf((float)(g_deg[i] + 1));
}
__global__ void fill_csr_kernel(const int* __restrict__ rowE, const int* __restrict__ colE) {
    int e = blockIdx.x * blockDim.x + threadIdx.x;
    if (e >= NE) return;
    int p = atomicAdd(&g_cursor[rowE[e]], 1);
    g_col[p] = colE[e];
}

// ---------------- fused prep: zero degrees + split/transpose all weights ----
#define CVT_TOTAL (32768 + 196608 + 16384)
__global__ void convert_w_all_kernel(const float* __restrict__ W0,
                                     const float* __restrict__ Wh,
                                     const float* __restrict__ Wl) {
    int i = blockIdx.x * 256 + threadIdx.x;
    if (i < NN) g_deg[i] = 0;
    if (i < 32768) {
        int n = i >> 7, k = i & 127;
        float v = W0[k * 256 + n];
        __nv_bfloat16 h = __float2bfloat16(v);
        g_w0hi[i] = h;
        g_w0lo[i] = __float2bfloat16(v - __bfloat162float(h));
    } else if (i < 229376) {
        int j = i - 32768;
        int l = j >> 16, r = j & 65535;
        int n = r >> 8, k = r & 255;
        float v = Wh[l * 65536 + k * 256 + n];
        __nv_bfloat16 h = __float2bfloat16(v);
        g_whhi[j] = h;
        g_whlo[j] = __float2bfloat16(v - __bfloat162float(h));
    } else if (i < CVT_TOTAL) {
        int j = i - 229376;
        int n = j >> 8, k = j & 255;
        float v = (n < D_O) ? Wl[k * D_O + n] : 0.f;
        __nv_bfloat16 h = __float2bfloat16(v);
        g_wlhi[j] = h;
        g_wllo[j] = __float2bfloat16(v - __bfloat162float(h));
    }
}

// ---------------- x -> fp16 -------------------------------------------------
__global__ void convert_x_kernel(const float* __restrict__ x, __half* __restrict__ xh) {
    int i = blockIdx.x * 256 + threadIdx.x;   // float4 index
    if (i >= NN * 32) return;
    float4 v = reinterpret_cast<const float4*>(x)[i];
    __half2 a = __floats2half2_rn(v.x, v.y);
    __half2 b = __floats2half2_rn(v.z, v.w);
    uint2 u;
    u.x = *reinterpret_cast<uint32_t*>(&a);
    u.y = *reinterpret_cast<uint32_t*>(&b);
    reinterpret_cast<uint2*>(xh)[i] = u;
}

// ---------------- pipelined warp-MMA split-bf16 GEMM ------------------------
// C[128 x NT] = f(A)[128 x KTOT] @ Wt[NT x KTOT]^T  (x dinv if SCALE)
// OUTH: write fp16 instead of fp32.
#define OF_ALO 16384
#define OF_BHI 32768

template <int KTOT, int NT, bool BN, bool SCALE, bool STATS, bool OUTH>
__global__ __launch_bounds__(512)
void gemm_mma_kernel(const float* __restrict__ A,
                     const __nv_bfloat16* __restrict__ Whi,
                     const __nv_bfloat16* __restrict__ Wlo,
                     void* __restrict__ Cv) {
    constexpr int STG = 32768 + 2 * NT * 128;
    constexpr int OF_BLO = 32768 + NT * 128;
    constexpr int NPW = NT / 4;
    constexpr int NI = NPW / 8;
    constexpr int KCH = KTOT / 64;

    extern __shared__ __align__(1024) char smem[];
    uint32_t sb = smem_u32(smem);
    int tid = threadIdx.x, lane = tid & 31, wid = tid >> 5;
    int wm = wid >> 2, wn = wid & 3;
    int rowBase = blockIdx.x * 128;

    float acc[2][NI][4];
    #pragma unroll
    for (int mi = 0; mi < 2; ++mi)
        #pragma unroll
        for (int ni = 0; ni < NI; ++ni)
            #pragma unroll
            for (int q = 0; q < 4; ++q) acc[mi][ni][q] = 0.f;

    int cg = (tid & 7) * 8;
    int rr = tid >> 3;
    float av[2][8];

    auto ldgA = [&](int ch) {
        int k0 = ch * 64;
        #pragma unroll
        for (int p = 0; p < 2; ++p) {
            int gr = rowBase + rr + p * 64;
            if (gr < NN) {
                const float4* ap = reinterpret_cast<const float4*>(A + (size_t)gr * KTOT + k0 + cg);
                float4 x0 = ap[0], x1 = ap[1];
                av[p][0] = x0.x; av[p][1] = x0.y; av[p][2] = x0.z; av[p][3] = x0.w;
                av[p][4] = x1.x; av[p][5] = x1.y; av[p][6] = x1.z; av[p][7] = x1.w;
            } else {
                #pragma unroll
                for (int j = 0; j < 8; ++j) av[p][j] = 0.f;
            }
        }
    };
    auto cpB = [&](int ch, int s) {
        int k0 = ch * 64;
        uint32_t base = sb + s * STG;
        #pragma unroll
        for (int p = 0; p < NT / 64; ++p) {
            int n = rr + p * 64;
            size_t go = (size_t)n * KTOT + k0 + cg;
            uint32_t off = SW128((uint32_t)(n * 128 + cg * 2));
            cp16(base + OF_BHI + off, Whi + go);
            cp16(base + OF_BLO + off, Wlo + go);
        }
    };
    auto stsA = [&](int ch, int s) {
        int k0 = ch * 64;
        char* base = smem + s * STG;
        #pragma unroll
        for (int p = 0; p < 2; ++p) {
            float v[8];
            #pragma unroll
            for (int j = 0; j < 8; ++j) v[j] = av[p][j];
            if (BN) {
                #pragma unroll
                for (int j = 0; j < 8; ++j) {
                    int c = k0 + cg + j;
                    v[j] = fmaxf(fmaf(v[j], g_scale[c], g_shift[c]), 0.f);
                }
            }
            __nv_bfloat16 hi8[8], lo8[8];
            #pragma unroll
            for (int j = 0; j < 8; ++j) {
                __nv_bfloat16 h = __float2bfloat16(v[j]);
                hi8[j] = h;
                lo8[j] = __float2bfloat16(v[j] - __bfloat162float(h));
            }
            uint32_t off = SW128((uint32_t)((rr + p * 64) * 128 + cg * 2));
            *reinterpret_cast<uint4*>(base + off) = *reinterpret_cast<uint4*>(hi8);
            *reinterpret_cast<uint4*>(base + OF_ALO + off) = *reinterpret_cast<uint4*>(lo8);
        }
    };
    auto domma = [&](int s) {
        uint32_t aHi = sb + s * STG;
        uint32_t aLo = aHi + OF_ALO;
        uint32_t bHi = aHi + OF_BHI;
        uint32_t bLo = aHi + OF_BLO;
        #pragma unroll
        for (int ks = 0; ks < 4; ++ks) {
            int kk = ks * 16;
            uint32_t ah[2][4], al[2][4];
            #pragma unroll
            for (int mi = 0; mi < 2; ++mi) {
                int r = wm * 32 + mi * 16 + (lane & 15);
                int c = kk + (lane >> 4) * 8;
                uint32_t off = SW128((uint32_t)(r * 128 + c * 2));
                ldm_x4(ah[mi], aHi + off);
                ldm_x4(al[mi], aLo + off);
            }
            #pragma unroll
            for (int nt = 0; nt < NI / 2; ++nt) {
                int g = lane >> 3;
                int row = wn * NPW + nt * 16 + (g >> 1) * 8 + (lane & 7);
                int c = kk + (g & 1) * 8;
                uint32_t off = SW128((uint32_t)(row * 128 + c * 2));
                uint32_t bh[4], bl_[4];
                ldm_x4(bh, bHi + off);
                ldm_x4(bl_, bLo + off);
                #pragma unroll
                for (int half = 0; half < 2; ++half) {
                    int ni = nt * 2 + half;
                    uint32_t b0h = bh[half * 2], b1h = bh[half * 2 + 1];
                    uint32_t b0l = bl_[half * 2], b1l = bl_[half * 2 + 1];
                    #pragma unroll
                    for (int mi = 0; mi < 2; ++mi) {
                        mma_bf16(acc[mi][ni], ah[mi], b0h, b1h);
                        mma_bf16(acc[mi][ni], ah[mi], b0l, b1l);
                        mma_bf16(acc[mi][ni], al[mi], b0h, b1h);
                    }
                }
            }
        }
    };

    ldgA(0);
    cpB(0, 0);
    CP_COMMIT();
    stsA(0, 0);

    for (int ch = 0; ch < KCH; ++ch) {
        int s = ch & 1;
        CP_WAIT0();
        __syncthreads();
        if (ch + 1 < KCH) {
            ldgA(ch + 1);
            cpB(ch + 1, s ^ 1);
            CP_COMMIT();
        }
        domma(s);
        if (ch + 1 < KCH) stsA(ch + 1, s ^ 1);
    }

    // epilogue
    #pragma unroll
    for (int mi = 0; mi < 2; ++mi) {
        int r0 = rowBase + wm * 32 + mi * 16 + (lane >> 2);
        int r1 = r0 + 8;
        float d0 = 1.f, d1 = 1.f;
        if (SCALE) {
            d0 = (r0 < NN) ? g_dinv[r0] : 0.f;
            d1 = (r1 < NN) ? g_dinv[r1] : 0.f;
        }
        #pragma unroll
        for (int ni = 0; ni < NI; ++ni) {
            int c0 = wn * NPW + ni * 8 + (lane & 3) * 2;
            if constexpr (OUTH) {
                __half* Ch = reinterpret_cast<__half*>(Cv);
                if (r0 < NN)
                    *reinterpret_cast<__half2*>(Ch + (size_t)r0 * NT + c0) =
                        __floats2half2_rn(acc[mi][ni][0] * d0, acc[mi][ni][1] * d0);
                if (r1 < NN)
                    *reinterpret_cast<__half2*>(Ch + (size_t)r1 * NT + c0) =
                        __floats2half2_rn(acc[mi][ni][2] * d1, acc[mi][ni][3] * d1);
            } else {
                float* Cf = reinterpret_cast<float*>(Cv);
                if (r0 < NN)
                    *reinterpret_cast<float2*>(Cf + (size_t)r0 * NT + c0) =
                        make_float2(acc[mi][ni][0] * d0, acc[mi][ni][1] * d0);
                if (r1 < NN)
                    *reinterpret_cast<float2*>(Cf + (size_t)r1 * NT + c0) =
                        make_float2(acc[mi][ni][2] * d1, acc[mi][ni][3] * d1);
            }
        }
    }

    // fused BN stats (layer-0 GEMM)
    if constexpr (STATS) {
        __shared__ float s_sum[256];
        __shared__ float s_sq[256];
        if (tid < 256) { s_sum[tid] = 0.f; s_sq[tid] = 0.f; }
        __syncthreads();
        #pragma unroll
        for (int ni = 0; ni < NI; ++ni) {
            float s0 = 0.f, q0 = 0.f, s1 = 0.f, q1 = 0.f;
            #pragma unroll
            for (int mi = 0; mi < 2; ++mi) {
                float va = acc[mi][ni][0], vb = acc[mi][ni][2];
                s0 += va + vb; q0 += va * va + vb * vb;
                float vc = acc[mi][ni][1], vd = acc[mi][ni][3];
                s1 += vc + vd; q1 += vc * vc + vd * vd;
            }
            #pragma unroll
            for (int off = 4; off <= 16; off <<= 1) {
                s0 += __shfl_xor_sync(0xffffffffu, s0, off);
                q0 += __shfl_xor_sync(0xffffffffu, q0, off);
                s1 += __shfl_xor_sync(0xffffffffu, s1, off);
                q1 += __shfl_xor_sync(0xffffffffu, q1, off);
            }
            if ((lane >> 2) == 0) {
                int c0 = wn * NPW + ni * 8 + (lane & 3) * 2;
                atomicAdd(&s_sum[c0], s0);
                atomicAdd(&s_sq[c0], q0);
                atomicAdd(&s_sum[c0 + 1], s1);
                atomicAdd(&s_sq[c0 + 1], q1);
            }
        }
        __syncthreads();
        if (tid < 256) {
            atomicAdd(&g_sum[tid], s_sum[tid]);
            atomicAdd(&g_sumsq[tid], s_sq[tid]);
        }
    }
}

// ---------------- SpMM over fp16 input, fp32 output -------------------------
// COLS halves per row (128 or 256); warp per row; lane handles COLS/32 cols.
template <bool WEIGHTED, bool STATS, int COLS>
__global__ __launch_bounds__(512)
void spmmh_kernel(const __half* __restrict__ in, float* __restrict__ out) {
    constexpr int CPL = COLS / 32;   // 4 or 8 halves per lane
    int warp = threadIdx.x >> 5, lane = threadIdx.x & 31;
    int row = blockIdx.x * 16 + warp;

    float acc[CPL];
    {
        const __half* p = in + (size_t)row * COLS + lane * CPL;
        float w = WEIGHTED ? g_dinv[row] : 1.f;
        if constexpr (CPL == 8) {
            uint4 u = *reinterpret_cast<const uint4*>(p);
            float2 f0 = __half22float2(*reinterpret_cast<__half2*>(&u.x));
            float2 f1 = __half22float2(*reinterpret_cast<__half2*>(&u.y));
            float2 f2 = __half22float2(*reinterpret_cast<__half2*>(&u.z));
            float2 f3 = __half22float2(*reinterpret_cast<__half2*>(&u.w));
            acc[0] = f0.x * w; acc[1] = f0.y * w; acc[2] = f1.x * w; acc[3] = f1.y * w;
            acc[4] = f2.x * w; acc[5] = f2.y * w; acc[6] = f3.x * w; acc[7] = f3.y * w;
        } else {
            uint2 u = *reinterpret_cast<const uint2*>(p);
            float2 f0 = __half22float2(*reinterpret_cast<__half2*>(&u.x));
            float2 f1 = __half22float2(*reinterpret_cast<__half2*>(&u.y));
            acc[0] = f0.x * w; acc[1] = f0.y * w; acc[2] = f1.x * w; acc[3] = f1.y * w;
        }
    }
    int s = g_rowptr[row], e = g_rowptr[row + 1];
    for (int i = s; i < e; ++i) {
        int c = g_col[i];
        const __half* p = in + (size_t)c * COLS + lane * CPL;
        float w = WEIGHTED ? g_dinv[c] : 1.f;
        if constexpr (CPL == 8) {
            uint4 u = *reinterpret_cast<const uint4*>(p);
            float2 f0 = __half22float2(*reinterpret_cast<__half2*>(&u.x));
            float2 f1 = __half22float2(*reinterpret_cast<__half2*>(&u.y));
            float2 f2 = __half22float2(*reinterpret_cast<__half2*>(&u.z));
            float2 f3 = __half22float2(*reinterpret_cast<__half2*>(&u.w));
            if (WEIGHTED) {
                acc[0] = fmaf(f0.x, w, acc[0]); acc[1] = fmaf(f0.y, w, acc[1]);
                acc[2] = fmaf(f1.x, w, acc[2]); acc[3] = fmaf(f1.y, w, acc[3]);
                acc[4] = fmaf(f2.x, w, acc[4]); acc[5] = fmaf(f2.y, w, acc[5]);
                acc[6] = fmaf(f3.x, w, acc[6]); acc[7] = fmaf(f3.y, w, acc[7]);
            } else {
                acc[0] += f0.x; acc[1] += f0.y; acc[2] += f1.x; acc[3] += f1.y;
                acc[4] += f2.x; acc[5] += f2.y; acc[6] += f3.x; acc[7] += f3.y;
            }
        } else {
            uint2 u = *reinterpret_cast<const uint2*>(p);
            float2 f0 = __half22float2(*reinterpret_cast<__half2*>(&u.x));
            float2 f1 = __half22float2(*reinterpret_cast<__half2*>(&u.y));
            if (WEIGHTED) {
                acc[0] = fmaf(f0.x, w, acc[0]); acc[1] = fmaf(f0.y, w, acc[1]);
                acc[2] = fmaf(f1.x, w, acc[2]); acc[3] = fmaf(f1.y, w, acc[3]);
            } else {
                acc[0] += f0.x; acc[1] += f0.y; acc[2] += f1.x; acc[3] += f1.y;
            }
        }
    }
    float d = g_dinv[row];
    #pragma unroll
    for (int j = 0; j < CPL; ++j) acc[j] *= d;
    float* op = out + (size_t)row * COLS + lane * CPL;
    #pragma unroll
    for (int j = 0; j < CPL; j += 4)
        *reinterpret_cast<float4*>(op + j) =
            make_float4(acc[j], acc[j + 1], acc[j + 2], acc[j + 3]);

    if constexpr (STATS) {
        __shared__ float ss[16][COLS];
        __shared__ float sq[16][COLS];
        #pragma unroll
        for (int j = 0; j < CPL; ++j) {
            ss[warp][lane * CPL + j] = acc[j];
            sq[warp][lane * CPL + j] = acc[j] * acc[j];
        }
        __syncthreads();
        int t = threadIdx.x;
        if (t < COLS) {
            float sm = 0.f;
            #pragma unroll
            for (int w = 0; w < 16; ++w) sm += ss[w][t];
            atomicAdd(&g_sum[t], sm);
        } else if (t < 2 * COLS) {
            int c = t - COLS;
            float sm = 0.f;
            #pragma unroll
            for (int w = 0; w < 16; ++w) sm += sq[w][c];
            atomicAdd(&g_sumsq[c], sm);
        }
    }
}

// ---------------- BN finalize (+reset stats for graph-replay determinism) ---
__global__ void bn_finalize_kernel(const float* __restrict__ gamma,
                                   const float* __restrict__ beta) {
    int c = threadIdx.x;
    float mu = g_sum[c] * (1.f / NN);
    float var = g_sumsq[c] * (1.f / NN) - mu * mu;
    float sc = rsqrtf(var + 1e-5f) * gamma[c];
    g_scale[c] = sc;
    g_shift[c] = beta[c] - mu * sc;
    g_sum[c] = 0.f;
    g_sumsq[c] = 0.f;
}

// ---------------- final SpMM (64-stride fp32 in, 40 cols) + log_softmax -----
__global__ __launch_bounds__(256)
void spmm40_softmax_kernel(const float* __restrict__ hs,
                           const float* __restrict__ bl,
                           float* __restrict__ out) {
    int warp = threadIdx.x >> 5, lane = threadIdx.x & 31;
    int row = blockIdx.x * 8 + warp;
    if (row >= NN) return;
    size_t rbase = (size_t)row * 64;
    float a0 = hs[rbase + lane];
    float a1 = (lane < 8) ? hs[rbase + 32 + lane] : 0.f;
    int s = g_rowptr[row], e = g_rowptr[row + 1];
    for (int i = s; i < e; ++i) {
        size_t cb = (size_t)g_col[i] * 64;
        a0 += hs[cb + lane];
        if (lane < 8) a1 += hs[cb + 32 + lane];
    }
    float d = g_dinv[row];
    float v0 = fmaf(a0, d, bl[lane]);
    float v1 = (lane < 8) ? fmaf(a1, d, bl[32 + lane]) : 0.f;

    float m = v0;
    if (lane < 8) m = fmaxf(m, v1);
    #pragma unroll
    for (int off = 16; off > 0; off >>= 1)
        m = fmaxf(m, __shfl_xor_sync(0xffffffffu, m, off));
    float sum = expf(v0 - m) + ((lane < 8) ? expf(v1 - m) : 0.f);
    #pragma unroll
    for (int off = 16; off > 0; off >>= 1)
        sum += __shfl_xor_sync(0xffffffffu, sum, off);
    float lse = logf(sum);
    size_t ob = (size_t)row * D_O;
    out[ob + lane] = v0 - m - lse;
    if (lane < 8) out[ob + 32 + lane] = v1 - m - lse;
}

// ---------------- launcher ---------------------------------------------------
extern "C" void kernel_launch(void* const* d_in, const int* in_sizes, int n_in,
                              void* d_out, int out_size) {
    const float* x     = (const float*)d_in[0];
    const float* W0    = (const float*)d_in[1];
    const float* Wh    = (const float*)d_in[3];
    const float* gamma = (const float*)d_in[5];
    const float* beta  = (const float*)d_in[6];
    const float* Wl    = (const float*)d_in[7];
    const float* bl    = (const float*)d_in[8];
    const int*   ei    = (const int*)d_in[9];
    const int* rowE = ei;
    const int* colE = ei + NE;
    float* out = (float*)d_out;

    float *pA = nullptr, *pB = nullptr;
    __half* pH = nullptr;
    __nv_bfloat16 *w0hi, *w0lo, *whhi, *whlo, *wlhi, *wllo;
    cudaGetSymbolAddress((void**)&pA, g_bufA);
    cudaGetSymbolAddress((void**)&pB, g_bufB);
    cudaGetSymbolAddress((void**)&pH, g_bufH);
    cudaGetSymbolAddress((void**)&w0hi, g_w0hi);
    cudaGetSymbolAddress((void**)&w0lo, g_w0lo);
    cudaGetSymbolAddress((void**)&whhi, g_whhi);
    cudaGetSymbolAddress((void**)&whlo, g_whlo);
    cudaGetSymbolAddress((void**)&wlhi, g_wlhi);
    cudaGetSymbolAddress((void**)&wllo, g_wllo);

    constexpr int SMEM256 = 2 * (32768 + 2 * 256 * 128);  // 196608
    constexpr int SMEM64  = 2 * (32768 + 2 * 64 * 128);   //  98304
    cudaFuncSetAttribute(gemm_mma_kernel<128, 256, false, false, true, false>,
                         cudaFuncAttributeMaxDynamicSharedMemorySize, SMEM256);
    cudaFuncSetAttribute(gemm_mma_kernel<256, 256, true, true, false, true>,
                         cudaFuncAttributeMaxDynamicSharedMemorySize, SMEM256);
    cudaFuncSetAttribute(gemm_mma_kernel<256, 64, true, true, false, false>,
                         cudaFuncAttributeMaxDynamicSharedMemorySize, SMEM64);

    const int EB = (NE + 255) / 256;
    const int NBLK = (NN + 255) / 256;
    const int MT = (NN + 127) / 128;
    const int SPB = NN / 16;

    // prep
    convert_w_all_kernel<<<(CVT_TOTAL + 255) / 256, 256>>>(W0, Wh, Wl);
    convert_x_kernel<<<(NN * 32 + 255) / 256, 256>>>(x, pH);
    count_deg_kernel<<<EB, 256>>>(rowE);
    scan1_kernel<<<SCAN_BLOCKS, 1024>>>();
    scan2_kernel<<<1, 128>>>();
    scan3_kernel<<<NBLK, 256>>>();
    fill_csr_kernel<<<EB, 256>>>(rowE, colE);

    // layer 0: weighted fp16 aggregate of x, then GEMM with fused BN stats
    spmmh_kernel<true, false, 128><<<SPB, 512>>>(pH, pA);
    gemm_mma_kernel<128, 256, false, false, true, false><<<MT, 512, SMEM256>>>(
        pA, w0hi, w0lo, pB);
    bn_finalize_kernel<<<1, 256>>>(gamma, beta);

    // hidden layers 1..3: GEMM(BN fold, dinv, fp16 out) -> single-pass SpMM
    for (int l = 0; l < 3; ++l) {
        gemm_mma_kernel<256, 256, true, true, false, true><<<MT, 512, SMEM256>>>(
            pB, whhi + (size_t)l * 65536, whlo + (size_t)l * 65536, pH);
        spmmh_kernel<false, true, 256><<<SPB, 512>>>(pH, pB);
        bn_finalize_kernel<<<1, 256>>>(gamma + (size_t)(l + 1) * D_H,
                                       beta + (size_t)(l + 1) * D_H);
    }

    // final layer (fp32 out, BN3 fold + dinv) + softmax SpMM
    gemm_mma_kernel<256, 64, true, true, false, false><<<MT, 512, SMEM64>>>(
        pB, wlhi, wllo, pA);
    spmm40_softmax_kernel<<<NN / 8, 256>>>(pA, bl, out);
}

// round 8
// speedup vs baseline: 2.6948x; 1.2024x over previous
#include <cuda_runtime.h>
#include <cuda_fp16.h>
#include <math.h>
#include <stdint.h>

#define NN    100000
#define NE    1600000
#define D_INF 128
#define D_H   256
#define D_O   40
#define SCAN_BLOCKS ((NN + 1023) / 1024)

// ---------------- scratch (device globals; no allocation allowed) ----------
__device__ __align__(256) __half g_bufHA[(size_t)NN * D_H];
__device__ __align__(256) __half g_bufHB[(size_t)NN * D_H];
__device__ int   g_deg[NN];
__device__ float g_dinv[NN];
__device__ int   g_rowptr[NN + 1];
__device__ int   g_cursor[NN];
__device__ int   g_col[NE];
__device__ int   g_bsum[256];
__device__ float g_sum[D_H];
__device__ float g_sumsq[D_H];
__device__ float g_scale[D_H];
__device__ float g_shift[D_H];
__device__ __align__(256) __half g_w0hi[256 * 128];
__device__ __align__(256) __half g_w0lo[256 * 128];
__device__ __align__(256) __half g_whhi[3 * 256 * 256];
__device__ __align__(256) __half g_whlo[3 * 256 * 256];
__device__ __align__(256) __half g_wlhi[64 * 256];
__device__ __align__(256) __half g_wllo[64 * 256];

// ---------------- helpers ----------------------------------------------------
__device__ __forceinline__ uint32_t smem_u32(const void* p) {
    uint32_t a;
    asm("{ .reg .u64 t; cvta.to.shared.u64 t, %1; cvt.u32.u64 %0, t; }" : "=r"(a) : "l"(p));
    return a;
}
#define SW128(o) ((o) ^ (((o) >> 3) & 0x70))

__device__ __forceinline__ void ldm_x4(uint32_t* r, uint32_t addr) {
    asm volatile("ldmatrix.sync.aligned.m8n8.x4.shared.b16 {%0,%1,%2,%3}, [%4];"
                 : "=r"(r[0]), "=r"(r[1]), "=r"(r[2]), "=r"(r[3]) : "r"(addr));
}
__device__ __forceinline__ void mma_f16(float* c, const uint32_t* a, uint32_t b0, uint32_t b1) {
    asm volatile(
        "mma.sync.aligned.m16n8k16.row.col.f32.f16.f16.f32 "
        "{%0,%1,%2,%3}, {%4,%5,%6,%7}, {%8,%9}, {%0,%1,%2,%3};"
        : "+f"(c[0]), "+f"(c[1]), "+f"(c[2]), "+f"(c[3])
        : "r"(a[0]), "r"(a[1]), "r"(a[2]), "r"(a[3]), "r"(b0), "r"(b1));
}
__device__ __forceinline__ void cp16(uint32_t dst, const void* src) {
    asm volatile("cp.async.cg.shared.global [%0], [%1], 16;" :: "r"(dst), "l"(src));
}
#define CP_COMMIT() asm volatile("cp.async.commit_group;" ::: "memory")
#define CP_WAIT0()  asm volatile("cp.async.wait_group 0;" ::: "memory")

// ---------------- graph preprocessing --------------------------------------
__global__ void count_deg_kernel(const int* __restrict__ rowE) {
    int e = blockIdx.x * blockDim.x + threadIdx.x;
    if (e < NE) atomicAdd(&g_deg[rowE[e]], 1);
}
__global__ void scan1_kernel() {
    __shared__ int sm[1024];
    int tid = threadIdx.x;
    int i = blockIdx.x * 1024 + tid;
    int v = (i < NN) ? g_deg[i] : 0;
    int x = v;
    sm[tid] = x;
    __syncthreads();
    #pragma unroll
    for (int off = 1; off < 1024; off <<= 1) {
        int t = (tid >= off) ? sm[tid - off] : 0;
        __syncthreads();
        x += t;
        sm[tid] = x;
        __syncthreads();
    }
    if (i < NN) g_rowptr[i] = x - v;
    if (tid == 1023) g_bsum[blockIdx.x] = x;
}
__global__ void scan2_kernel() {
    __shared__ int sm[128];
    int tid = threadIdx.x;
    int v = (tid < SCAN_BLOCKS) ? g_bsum[tid] : 0;
    int x = v;
    sm[tid] = x;
    __syncthreads();
    #pragma unroll
    for (int off = 1; off < 128; off <<= 1) {
        int t = (tid >= off) ? sm[tid - off] : 0;
        __syncthreads();
        x += t;
        sm[tid] = x;
        __syncthreads();
    }
    if (tid < SCAN_BLOCKS) g_bsum[tid] = x - v;
    if (tid == 127) g_rowptr[NN] = x;
}
__global__ void scan3_kernel() {
    int i = blockIdx.x * blockDim.x + threadIdx.x;
    if (i >= NN) return;
    int rp = g_rowptr[i] + g_bsum[i >> 10];
    g_rowptr[i] = rp;
    g_cursor[i] = rp;
    g_dinv[i] = rsqrtf((float)(g_deg[i] + 1));
}
__global__ void fill_csr_kernel(const int* __restrict__ rowE, const int* __restrict__ colE) {
    int e = blockIdx.x * blockDim.x + threadIdx.x;
    if (e >= NE) return;
    int p = atomicAdd(&g_cursor[rowE[e]], 1);
    g_col[p] = colE[e];
}

// ---------------- fused prep: zero degrees + split/transpose all weights ----
// fp16 hi/lo split: Whi = fp16(W), Wlo = fp16(W - Whi)
#define CVT_TOTAL (32768 + 196608 + 16384)
__global__ void convert_w_all_kernel(const float* __restrict__ W0,
                                     const float* __restrict__ Wh,
                                     const float* __restrict__ Wl) {
    int i = blockIdx.x * 256 + threadIdx.x;
    if (i < NN) g_deg[i] = 0;
    if (i < 32768) {
        int n = i >> 7, k = i & 127;
        float v = W0[k * 256 + n];
        __half h = __float2half_rn(v);
        g_w0hi[i] = h;
        g_w0lo[i] = __float2half_rn(v - __half2float(h));
    } else if (i < 229376) {
        int j = i - 32768;
        int l = j >> 16, r = j & 65535;
        int n = r >> 8, k = r & 255;
        float v = Wh[l * 65536 + k * 256 + n];
        __half h = __float2half_rn(v);
        g_whhi[j] = h;
        g_whlo[j] = __float2half_rn(v - __half2float(h));
    } else if (i < CVT_TOTAL) {
        int j = i - 229376;
        int n = j >> 8, k = j & 255;
        float v = (n < D_O) ? Wl[k * D_O + n] : 0.f;
        __half h = __float2half_rn(v);
        g_wlhi[j] = h;
        g_wllo[j] = __float2half_rn(v - __half2float(h));
    }
}

// ---------------- x -> fp16 -------------------------------------------------
__global__ void convert_x_kernel(const float* __restrict__ x, __half* __restrict__ xh) {
    int i = blockIdx.x * 256 + threadIdx.x;   // float4 index
    if (i >= NN * 32) return;
    float4 v = reinterpret_cast<const float4*>(x)[i];
    __half2 a = __floats2half2_rn(v.x, v.y);
    __half2 b = __floats2half2_rn(v.z, v.w);
    uint2 u;
    u.x = *reinterpret_cast<uint32_t*>(&a);
    u.y = *reinterpret_cast<uint32_t*>(&b);
    reinterpret_cast<uint2*>(xh)[i] = u;
}

// ---------------- pipelined warp-MMA 2-product fp16 GEMM --------------------
// C[128 x NT] = f(A)[128 x KTOT] @ (Whi+Wlo)[NT x KTOT]^T  (x dinv if SCALE)
// A fp16 (single); BN: convert through registers; else pure cp.async copy.
template <int KTOT, int NT, bool BN, bool SCALE, bool STATS>
__global__ __launch_bounds__(512)
void gemm_mma_kernel(const __half* __restrict__ A,
                     const __half* __restrict__ Whi,
                     const __half* __restrict__ Wlo,
                     __half* __restrict__ C) {
    constexpr int OF_BHI = 16384;                 // A: 128 rows x 128B
    constexpr int OF_BLO = 16384 + NT * 128;
    constexpr int STG = 16384 + 2 * NT * 128;
    constexpr int NPW = NT / 4;
    constexpr int NI = NPW / 8;
    constexpr int KCH = KTOT / 64;

    extern __shared__ __align__(1024) char smem[];
    uint32_t sb = smem_u32(smem);
    int tid = threadIdx.x, lane = tid & 31, wid = tid >> 5;
    int wm = wid >> 2, wn = wid & 3;
    int rowBase = blockIdx.x * 128;

    float acc[2][NI][4];
    #pragma unroll
    for (int mi = 0; mi < 2; ++mi)
        #pragma unroll
        for (int ni = 0; ni < NI; ++ni)
            #pragma unroll
            for (int q = 0; q < 4; ++q) acc[mi][ni][q] = 0.f;

    int cg = (tid & 7) * 8;   // fp16-element offset within 64-col chunk
    int rr = tid >> 3;        // 0..63
    uint4 av[2];              // A prefetch (BN path): 2 rows x 8 fp16

    auto ldgA = [&](int ch) {       // BN path: load to regs
        int k0 = ch * 64;
        #pragma unroll
        for (int p = 0; p < 2; ++p) {
            int gr = rowBase + rr + p * 64;
            if (gr < NN)
                av[p] = *reinterpret_cast<const uint4*>(A + (size_t)gr * KTOT + k0 + cg);
            else
                av[p] = make_uint4(0, 0, 0, 0);
        }
    };
    auto stsA = [&](int ch, int s) {  // BN path: convert + store
        int k0 = ch * 64;
        char* base = smem + s * STG;
        #pragma unroll
        for (int p = 0; p < 2; ++p) {
            __half2* hp = reinterpret_cast<__half2*>(&av[p]);
            uint4 o;
            __half2* op = reinterpret_cast<__half2*>(&o);
            #pragma unroll
            for (int j = 0; j < 4; ++j) {
                float2 f = __half22float2(hp[j]);
                int c = k0 + cg + j * 2;
                f.x = fmaxf(fmaf(f.x, g_scale[c], g_shift[c]), 0.f);
                f.y = fmaxf(fmaf(f.y, g_scale[c + 1], g_shift[c + 1]), 0.f);
                op[j] = __floats2half2_rn(f.x, f.y);
            }
            uint32_t off = SW128((uint32_t)((rr + p * 64) * 128 + cg * 2));
            *reinterpret_cast<uint4*>(base + off) = o;
        }
    };
    auto cpA = [&](int ch, int s) {   // no-BN path: direct async copy
        int k0 = ch * 64;
        uint32_t base = sb + s * STG;
        #pragma unroll
        for (int p = 0; p < 2; ++p) {
            int gr = rowBase + rr + p * 64;
            uint32_t off = SW128((uint32_t)((rr + p * 64) * 128 + cg * 2));
            // gr < NN always has valid storage (buffer is NN*256 >= padded reads? guard):
            if (gr < NN)
                cp16(base + off, A + (size_t)gr * KTOT + k0 + cg);
            else
                *reinterpret_cast<uint4*>(smem + s * STG + off) = make_uint4(0, 0, 0, 0);
        }
    };
    auto cpB = [&](int ch, int s) {
        int k0 = ch * 64;
        uint32_t base = sb + s * STG;
        #pragma unroll
        for (int p = 0; p < NT / 64; ++p) {
            int n = rr + p * 64;
            size_t go = (size_t)n * KTOT + k0 + cg;
            uint32_t off = SW128((uint32_t)(n * 128 + cg * 2));
            cp16(base + OF_BHI + off, Whi + go);
            cp16(base + OF_BLO + off, Wlo + go);
        }
    };
    auto domma = [&](int s) {
        uint32_t aF = sb + s * STG;
        uint32_t bHi = aF + OF_BHI;
        uint32_t bLo = aF + OF_BLO;
        #pragma unroll
        for (int ks = 0; ks < 4; ++ks) {
            int kk = ks * 16;
            uint32_t af[2][4];
            #pragma unroll
            for (int mi = 0; mi < 2; ++mi) {
                int r = wm * 32 + mi * 16 + (lane & 15);
                int c = kk + (lane >> 4) * 8;
                uint32_t off = SW128((uint32_t)(r * 128 + c * 2));
                ldm_x4(af[mi], aF + off);
            }
            #pragma unroll
            for (int nt = 0; nt < NI / 2; ++nt) {
                int g = lane >> 3;
                int row = wn * NPW + nt * 16 + (g >> 1) * 8 + (lane & 7);
                int c = kk + (g & 1) * 8;
                uint32_t off = SW128((uint32_t)(row * 128 + c * 2));
                uint32_t bh[4], bl_[4];
                ldm_x4(bh, bHi + off);
                ldm_x4(bl_, bLo + off);
                #pragma unroll
                for (int half = 0; half < 2; ++half) {
                    int ni = nt * 2 + half;
                    #pragma unroll
                    for (int mi = 0; mi < 2; ++mi) {
                        mma_f16(acc[mi][ni], af[mi], bh[half * 2], bh[half * 2 + 1]);
                        mma_f16(acc[mi][ni], af[mi], bl_[half * 2], bl_[half * 2 + 1]);
                    }
                }
            }
        }
    };

    if (BN) ldgA(0); else cpA(0, 0);
    cpB(0, 0);
    CP_COMMIT();
    if (BN) stsA(0, 0);

    for (int ch = 0; ch < KCH; ++ch) {
        int s = ch & 1;
        CP_WAIT0();
        __syncthreads();
        if (ch + 1 < KCH) {
            if (BN) ldgA(ch + 1); else cpA(ch + 1, s ^ 1);
            cpB(ch + 1, s ^ 1);
            CP_COMMIT();
        }
        domma(s);
        if (BN && ch + 1 < KCH) stsA(ch + 1, s ^ 1);
    }

    // epilogue: fp16 store (x dinv if SCALE)
    #pragma unroll
    for (int mi = 0; mi < 2; ++mi) {
        int r0 = rowBase + wm * 32 + mi * 16 + (lane >> 2);
        int r1 = r0 + 8;
        float d0 = 1.f, d1 = 1.f;
        if (SCALE) {
            d0 = (r0 < NN) ? g_dinv[r0] : 0.f;
            d1 = (r1 < NN) ? g_dinv[r1] : 0.f;
        }
        #pragma unroll
        for (int ni = 0; ni < NI; ++ni) {
            int c0 = wn * NPW + ni * 8 + (lane & 3) * 2;
            if (r0 < NN)
                *reinterpret_cast<__half2*>(C + (size_t)r0 * NT + c0) =
                    __floats2half2_rn(acc[mi][ni][0] * d0, acc[mi][ni][1] * d0);
            if (r1 < NN)
                *reinterpret_cast<__half2*>(C + (size_t)r1 * NT + c0) =
                    __floats2half2_rn(acc[mi][ni][2] * d1, acc[mi][ni][3] * d1);
        }
    }

    // fused BN stats (layer-0 GEMM): fp32 accumulators, padding rows are zero
    if constexpr (STATS) {
        __shared__ float s_sum[256];
        __shared__ float s_sq[256];
        if (tid < 256) { s_sum[tid] = 0.f; s_sq[tid] = 0.f; }
        __syncthreads();
        #pragma unroll
        for (int ni = 0; ni < NI; ++ni) {
            float s0 = 0.f, q0 = 0.f, s1 = 0.f, q1 = 0.f;
            #pragma unroll
            for (int mi = 0; mi < 2; ++mi) {
                float va = acc[mi][ni][0], vb = acc[mi][ni][2];
                s0 += va + vb; q0 += va * va + vb * vb;
                float vc = acc[mi][ni][1], vd = acc[mi][ni][3];
                s1 += vc + vd; q1 += vc * vc + vd * vd;
            }
            #pragma unroll
            for (int off = 4; off <= 16; off <<= 1) {
                s0 += __shfl_xor_sync(0xffffffffu, s0, off);
                q0 += __shfl_xor_sync(0xffffffffu, q0, off);
                s1 += __shfl_xor_sync(0xffffffffu, s1, off);
                q1 += __shfl_xor_sync(0xffffffffu, q1, off);
            }
            if ((lane >> 2) == 0) {
                int c0 = wn * NPW + ni * 8 + (lane & 3) * 2;
                atomicAdd(&s_sum[c0], s0);
                atomicAdd(&s_sq[c0], q0);
                atomicAdd(&s_sum[c0 + 1], s1);
                atomicAdd(&s_sq[c0 + 1], q1);
            }
        }
        __syncthreads();
        if (tid < 256) {
            atomicAdd(&g_sum[tid], s_sum[tid]);
            atomicAdd(&g_sumsq[tid], s_sq[tid]);
        }
    }
}

// ---------------- SpMM fp16 in -> fp16 out (+fp32 stats) --------------------
template <bool WEIGHTED, bool STATS, int COLS>
__global__ __launch_bounds__(512)
void spmmh_kernel(const __half* __restrict__ in, __half* __restrict__ out) {
    constexpr int CPL = COLS / 32;   // 4 or 8 halves per lane
    int warp = threadIdx.x >> 5, lane = threadIdx.x & 31;
    int row = blockIdx.x * 16 + warp;

    float acc[CPL];
    {
        const __half2* p = reinterpret_cast<const __half2*>(in + (size_t)row * COLS + lane * CPL);
        float w = WEIGHTED ? g_dinv[row] : 1.f;
        #pragma unroll
        for (int j = 0; j < CPL / 2; ++j) {
            float2 f = __half22float2(p[j]);
            acc[j * 2] = f.x * w;
            acc[j * 2 + 1] = f.y * w;
        }
    }
    int s = g_rowptr[row], e = g_rowptr[row + 1];
    for (int i = s; i < e; ++i) {
        int c = g_col[i];
        const __half* p = in + (size_t)c * COLS + lane * CPL;
        float w = WEIGHTED ? g_dinv[c] : 1.f;
        if constexpr (CPL == 8) {
            uint4 u = *reinterpret_cast<const uint4*>(p);
            __half2* hp = reinterpret_cast<__half2*>(&u);
            #pragma unroll
            for (int j = 0; j < 4; ++j) {
                float2 f = __half22float2(hp[j]);
                if (WEIGHTED) {
                    acc[j * 2] = fmaf(f.x, w, acc[j * 2]);
                    acc[j * 2 + 1] = fmaf(f.y, w, acc[j * 2 + 1]);
                } else {
                    acc[j * 2] += f.x;
                    acc[j * 2 + 1] += f.y;
                }
            }
        } else {
            uint2 u = *reinterpret_cast<const uint2*>(p);
            __half2* hp = reinterpret_cast<__half2*>(&u);
            #pragma unroll
            for (int j = 0; j < 2; ++j) {
                float2 f = __half22float2(hp[j]);
                if (WEIGHTED) {
                    acc[j * 2] = fmaf(f.x, w, acc[j * 2]);
                    acc[j * 2 + 1] = fmaf(f.y, w, acc[j * 2 + 1]);
                } else {
                    acc[j * 2] += f.x;
                    acc[j * 2 + 1] += f.y;
                }
            }
        }
    }
    float d = g_dinv[row];
    #pragma unroll
    for (int j = 0; j < CPL; ++j) acc[j] *= d;

    {   // fp16 store
        __half2 o[CPL / 2];
        #pragma unroll
        for (int j = 0; j < CPL / 2; ++j)
            o[j] = __floats2half2_rn(acc[j * 2], acc[j * 2 + 1]);
        __half* op = out + (size_t)row * COLS + lane * CPL;
        if constexpr (CPL == 8)
            *reinterpret_cast<uint4*>(op) = *reinterpret_cast<uint4*>(o);
        else
            *reinterpret_cast<uint2*>(op) = *reinterpret_cast<uint2*>(o);
    }

    if constexpr (STATS) {
        __shared__ float ss[16][COLS];
        __shared__ float sq[16][COLS];
        #pragma unroll
        for (int j = 0; j < CPL; ++j) {
            ss[warp][lane * CPL + j] = acc[j];
            sq[warp][lane * CPL + j] = acc[j] * acc[j];
        }
        __syncthreads();
        int t = threadIdx.x;
        if (t < COLS) {
            float sm = 0.f;
            #pragma unroll
            for (int w = 0; w < 16; ++w) sm += ss[w][t];
            atomicAdd(&g_sum[t], sm);
        } else if (t < 2 * COLS) {
            int c = t - COLS;
            float sm = 0.f;
            #pragma unroll
            for (int w = 0; w < 16; ++w) sm += sq[w][c];
            atomicAdd(&g_sumsq[c], sm);
        }
    }
}

// ---------------- BN finalize (+reset stats for graph-replay determinism) ---
__global__ void bn_finalize_kernel(const float* __restrict__ gamma,
                                   const float* __restrict__ beta) {
    int c = threadIdx.x;
    float mu = g_sum[c] * (1.f / NN);
    float var = g_sumsq[c] * (1.f / NN) - mu * mu;
    float sc = rsqrtf(var + 1e-5f) * gamma[c];
    g_scale[c] = sc;
    g_shift[c] = beta[c] - mu * sc;
    g_sum[c] = 0.f;
    g_sumsq[c] = 0.f;
}

// ---------------- final SpMM (64-stride fp16 in, 40 cols) + log_softmax -----
__global__ __launch_bounds__(256)
void spmm40_softmax_kernel(const __half* __restrict__ hs,
                           const float* __restrict__ bl,
                           float* __restrict__ out) {
    int warp = threadIdx.x >> 5, lane = threadIdx.x & 31;
    int row = blockIdx.x * 8 + warp;
    if (row >= NN) return;
    size_t rbase = (size_t)row * 64;
    float a0 = __half2float(hs[rbase + lane]);
    float a1 = (lane < 8) ? __half2float(hs[rbase + 32 + lane]) : 0.f;
    int s = g_rowptr[row], e = g_rowptr[row + 1];
    for (int i = s; i < e; ++i) {
        size_t cb = (size_t)g_col[i] * 64;
        a0 += __half2float(hs[cb + lane]);
        if (lane < 8) a1 += __half2float(hs[cb + 32 + lane]);
    }
    float d = g_dinv[row];
    float v0 = fmaf(a0, d, bl[lane]);
    float v1 = (lane < 8) ? fmaf(a1, d, bl[32 + lane]) : 0.f;

    float m = v0;
    if (lane < 8) m = fmaxf(m, v1);
    #pragma unroll
    for (int off = 16; off > 0; off >>= 1)
        m = fmaxf(m, __shfl_xor_sync(0xffffffffu, m, off));
    float sum = expf(v0 - m) + ((lane < 8) ? expf(v1 - m) : 0.f);
    #pragma unroll
    for (int off = 16; off > 0; off >>= 1)
        sum += __shfl_xor_sync(0xffffffffu, sum, off);
    float lse = logf(sum);
    size_t ob = (size_t)row * D_O;
    out[ob + lane] = v0 - m - lse;
    if (lane < 8) out[ob + 32 + lane] = v1 - m - lse;
}

// ---------------- launcher ---------------------------------------------------
extern "C" void kernel_launch(void* const* d_in, const int* in_sizes, int n_in,
                              void* d_out, int out_size) {
    const float* x     = (const float*)d_in[0];
    const float* W0    = (const float*)d_in[1];
    const float* Wh    = (const float*)d_in[3];
    const float* gamma = (const float*)d_in[5];
    const float* beta  = (const float*)d_in[6];
    const float* Wl    = (const float*)d_in[7];
    const float* bl    = (const float*)d_in[8];
    const int*   ei    = (const int*)d_in[9];
    const int* rowE = ei;
    const int* colE = ei + NE;
    float* out = (float*)d_out;

    __half *pHA, *pHB, *w0hi, *w0lo, *whhi, *whlo, *wlhi, *wllo;
    cudaGetSymbolAddress((void**)&pHA, g_bufHA);
    cudaGetSymbolAddress((void**)&pHB, g_bufHB);
    cudaGetSymbolAddress((void**)&w0hi, g_w0hi);
    cudaGetSymbolAddress((void**)&w0lo, g_w0lo);
    cudaGetSymbolAddress((void**)&whhi, g_whhi);
    cudaGetSymbolAddress((void**)&whlo, g_whlo);
    cudaGetSymbolAddress((void**)&wlhi, g_wlhi);
    cudaGetSymbolAddress((void**)&wllo, g_wllo);

    constexpr int SMEM256 = 2 * (16384 + 2 * 256 * 128);  // 163840
    constexpr int SMEM64  = 2 * (16384 + 2 * 64 * 128);   //  65536
    cudaFuncSetAttribute(gemm_mma_kernel<128, 256, false, false, true>,
                         cudaFuncAttributeMaxDynamicSharedMemorySize, SMEM256);
    cudaFuncSetAttribute(gemm_mma_kernel<256, 256, true, true, false>,
                         cudaFuncAttributeMaxDynamicSharedMemorySize, SMEM256);
    cudaFuncSetAttribute(gemm_mma_kernel<256, 64, true, true, false>,
                         cudaFuncAttributeMaxDynamicSharedMemorySize, SMEM64);

    const int EB = (NE + 255) / 256;
    const int NBLK = (NN + 255) / 256;
    const int MT = (NN + 127) / 128;
    const int SPB = NN / 16;

    // prep
    convert_w_all_kernel<<<(CVT_TOTAL + 255) / 256, 256>>>(W0, Wh, Wl);
    convert_x_kernel<<<(NN * 32 + 255) / 256, 256>>>(x, pHA);
    count_deg_kernel<<<EB, 256>>>(rowE);
    scan1_kernel<<<SCAN_BLOCKS, 1024>>>();
    scan2_kernel<<<1, 128>>>();
    scan3_kernel<<<NBLK, 256>>>();
    fill_csr_kernel<<<EB, 256>>>(rowE, colE);

    // layer 0: weighted fp16 aggregate of x -> GEMM (cp.async A) + BN stats
    spmmh_kernel<true, false, 128><<<SPB, 512>>>(pHA, pHB);
    gemm_mma_kernel<128, 256, false, false, true><<<MT, 512, SMEM256>>>(
        pHB, w0hi, w0lo, pHA);
    bn_finalize_kernel<<<1, 256>>>(gamma, beta);

    // hidden layers 1..3: GEMM(BN fold, dinv) -> SpMM(+stats), all fp16
    for (int l = 0; l < 3; ++l) {
        gemm_mma_kernel<256, 256, true, true, false><<<MT, 512, SMEM256>>>(
            pHA, whhi + (size_t)l * 65536, whlo + (size_t)l * 65536, pHB);
        spmmh_kernel<false, true, 256><<<SPB, 512>>>(pHB, pHA);
        bn_finalize_kernel<<<1, 256>>>(gamma + (size_t)(l + 1) * D_H,
                                       beta + (size_t)(l + 1) * D_H);
    }

    // final layer (fp16 logits, BN3 fold + dinv) + softmax SpMM
    gemm_mma_kernel<256, 64, true, true, false><<<MT, 512, SMEM64>>>(
        pHA, wlhi, wllo, pHB);
    spmm40_softmax_kernel<<<NN / 8, 256>>>(pHB, bl, out);
}

// round 9
// speedup vs baseline: 3.0495x; 1.1316x over previous
#include <cuda_runtime.h>
#include <cuda_fp16.h>
#include <math.h>
#include <stdint.h>

#define NN    100000
#define NE    1600000
#define D_INF 128
#define D_H   256
#define D_O   40
#define SCAN_BLOCKS ((NN + 1023) / 1024)

// ---------------- scratch (device globals; no allocation allowed) ----------
__device__ __align__(256) __half g_bufHA[(size_t)NN * D_H];
__device__ __align__(256) __half g_bufHB[(size_t)NN * D_H];
__device__ int   g_deg[NN];
__device__ float g_dinv[NN];
__device__ int   g_rowptr[NN + 1];
__device__ int   g_cursor[NN];
__device__ int   g_col[NE];
__device__ int   g_bsum[256];
__device__ float g_sum[D_H];
__device__ float g_sumsq[D_H];
__device__ float g_scale[D_H];
__device__ float g_shift[D_H];
__device__ __align__(256) __half g_w0[256 * 128];
__device__ __align__(256) __half g_wh[3 * 256 * 256];
__device__ __align__(256) __half g_wl[64 * 256];

// ---------------- helpers ----------------------------------------------------
__device__ __forceinline__ uint32_t smem_u32(const void* p) {
    uint32_t a;
    asm("{ .reg .u64 t; cvta.to.shared.u64 t, %1; cvt.u32.u64 %0, t; }" : "=r"(a) : "l"(p));
    return a;
}
#define SW128(o) ((o) ^ (((o) >> 3) & 0x70))

__device__ __forceinline__ void ldm_x4(uint32_t* r, uint32_t addr) {
    asm volatile("ldmatrix.sync.aligned.m8n8.x4.shared.b16 {%0,%1,%2,%3}, [%4];"
                 : "=r"(r[0]), "=r"(r[1]), "=r"(r[2]), "=r"(r[3]) : "r"(addr));
}
__device__ __forceinline__ void mma_f16(float* c, const uint32_t* a, uint32_t b0, uint32_t b1) {
    asm volatile(
        "mma.sync.aligned.m16n8k16.row.col.f32.f16.f16.f32 "
        "{%0,%1,%2,%3}, {%4,%5,%6,%7}, {%8,%9}, {%0,%1,%2,%3};"
        : "+f"(c[0]), "+f"(c[1]), "+f"(c[2]), "+f"(c[3])
        : "r"(a[0]), "r"(a[1]), "r"(a[2]), "r"(a[3]), "r"(b0), "r"(b1));
}
__device__ __forceinline__ void cp16(uint32_t dst, const void* src) {
    asm volatile("cp.async.cg.shared.global [%0], [%1], 16;" :: "r"(dst), "l"(src));
}
#define CP_COMMIT() asm volatile("cp.async.commit_group;" ::: "memory")
#define CP_WAIT0()  asm volatile("cp.async.wait_group 0;" ::: "memory")

// ---------------- graph preprocessing --------------------------------------
__global__ void count_deg_kernel(const int* __restrict__ rowE) {
    int e = blockIdx.x * blockDim.x + threadIdx.x;
    if (e < NE) atomicAdd(&g_deg[rowE[e]], 1);
}
__global__ void scan1_kernel() {
    __shared__ int sm[1024];
    int tid = threadIdx.x;
    int i = blockIdx.x * 1024 + tid;
    int v = (i < NN) ? g_deg[i] : 0;
    int x = v;
    sm[tid] = x;
    __syncthreads();
    #pragma unroll
    for (int off = 1; off < 1024; off <<= 1) {
        int t = (tid >= off) ? sm[tid - off] : 0;
        __syncthreads();
        x += t;
        sm[tid] = x;
        __syncthreads();
    }
    if (i < NN) g_rowptr[i] = x - v;
    if (tid == 1023) g_bsum[blockIdx.x] = x;
}
__global__ void scan2_kernel() {
    __shared__ int sm[128];
    int tid = threadIdx.x;
    int v = (tid < SCAN_BLOCKS) ? g_bsum[tid] : 0;
    int x = v;
    sm[tid] = x;
    __syncthreads();
    #pragma unroll
    for (int off = 1; off < 128; off <<= 1) {
        int t = (tid >= off) ? sm[tid - off] : 0;
        __syncthreads();
        x += t;
        sm[tid] = x;
        __syncthreads();
    }
    if (tid < SCAN_BLOCKS) g_bsum[tid] = x - v;
    if (tid == 127) g_rowptr[NN] = x;
}
__global__ void scan3_kernel() {
    int i = blockIdx.x * blockDim.x + threadIdx.x;
    if (i >= NN) return;
    int rp = g_rowptr[i] + g_bsum[i >> 10];
    g_rowptr[i] = rp;
    g_cursor[i] = rp;
    g_dinv[i] = rsqrtf((float)(g_deg[i] + 1));
}
__global__ void fill_csr_kernel(const int* __restrict__ rowE, const int* __restrict__ colE) {
    int e = blockIdx.x * blockDim.x + threadIdx.x;
    if (e >= NE) return;
    int p = atomicAdd(&g_cursor[rowE[e]], 1);
    g_col[p] = colE[e];
}

// ---------------- fused prep: zero degrees + transpose/convert weights ------
#define CVT_TOTAL (32768 + 196608 + 16384)
__global__ void convert_w_all_kernel(const float* __restrict__ W0,
                                     const float* __restrict__ Wh,
                                     const float* __restrict__ Wl) {
    int i = blockIdx.x * 256 + threadIdx.x;
    if (i < NN) g_deg[i] = 0;
    if (i < 32768) {
        int n = i >> 7, k = i & 127;
        g_w0[i] = __float2half_rn(W0[k * 256 + n]);
    } else if (i < 229376) {
        int j = i - 32768;
        int l = j >> 16, r = j & 65535;
        int n = r >> 8, k = r & 255;
        g_wh[j] = __float2half_rn(Wh[l * 65536 + k * 256 + n]);
    } else if (i < CVT_TOTAL) {
        int j = i - 229376;
        int n = j >> 8, k = j & 255;
        g_wl[j] = __float2half_rn((n < D_O) ? Wl[k * D_O + n] : 0.f);
    }
}

// ---------------- x -> fp16 -------------------------------------------------
__global__ void convert_x_kernel(const float* __restrict__ x, __half* __restrict__ xh) {
    int i = blockIdx.x * 256 + threadIdx.x;   // float4 index
    if (i >= NN * 32) return;
    float4 v = reinterpret_cast<const float4*>(x)[i];
    __half2 a = __floats2half2_rn(v.x, v.y);
    __half2 b = __floats2half2_rn(v.z, v.w);
    uint2 u;
    u.x = *reinterpret_cast<uint32_t*>(&a);
    u.y = *reinterpret_cast<uint32_t*>(&b);
    reinterpret_cast<uint2*>(xh)[i] = u;
}

// ---------------- pipelined warp-MMA single-product fp16 GEMM ---------------
// C[128 x NT] = f(A)[128 x KTOT] @ W[NT x KTOT]^T  (x dinv if SCALE)
template <int KTOT, int NT, bool BN, bool SCALE, bool STATS>
__global__ __launch_bounds__(512)
void gemm_mma_kernel(const __half* __restrict__ A,
                     const __half* __restrict__ W,
                     __half* __restrict__ C) {
    constexpr int OF_B = 16384;               // A: 128 rows x 128B
    constexpr int STG = 16384 + NT * 128;
    constexpr int NPW = NT / 4;
    constexpr int NI = NPW / 8;
    constexpr int KCH = KTOT / 64;

    extern __shared__ __align__(1024) char smem[];
    uint32_t sb = smem_u32(smem);
    int tid = threadIdx.x, lane = tid & 31, wid = tid >> 5;
    int wm = wid >> 2, wn = wid & 3;
    int rowBase = blockIdx.x * 128;

    float acc[2][NI][4];
    #pragma unroll
    for (int mi = 0; mi < 2; ++mi)
        #pragma unroll
        for (int ni = 0; ni < NI; ++ni)
            #pragma unroll
            for (int q = 0; q < 4; ++q) acc[mi][ni][q] = 0.f;

    int cg = (tid & 7) * 8;
    int rr = tid >> 3;
    uint4 av[2];

    auto ldgA = [&](int ch) {
        int k0 = ch * 64;
        #pragma unroll
        for (int p = 0; p < 2; ++p) {
            int gr = rowBase + rr + p * 64;
            if (gr < NN)
                av[p] = *reinterpret_cast<const uint4*>(A + (size_t)gr * KTOT + k0 + cg);
            else
                av[p] = make_uint4(0, 0, 0, 0);
        }
    };
    auto stsA = [&](int ch, int s) {
        int k0 = ch * 64;
        char* base = smem + s * STG;
        #pragma unroll
        for (int p = 0; p < 2; ++p) {
            __half2* hp = reinterpret_cast<__half2*>(&av[p]);
            uint4 o;
            __half2* op = reinterpret_cast<__half2*>(&o);
            #pragma unroll
            for (int j = 0; j < 4; ++j) {
                float2 f = __half22float2(hp[j]);
                int c = k0 + cg + j * 2;
                f.x = fmaxf(fmaf(f.x, g_scale[c], g_shift[c]), 0.f);
                f.y = fmaxf(fmaf(f.y, g_scale[c + 1], g_shift[c + 1]), 0.f);
                op[j] = __floats2half2_rn(f.x, f.y);
            }
            uint32_t off = SW128((uint32_t)((rr + p * 64) * 128 + cg * 2));
            *reinterpret_cast<uint4*>(base + off) = o;
        }
    };
    auto cpA = [&](int ch, int s) {
        int k0 = ch * 64;
        uint32_t base = sb + s * STG;
        #pragma unroll
        for (int p = 0; p < 2; ++p) {
            int gr = rowBase + rr + p * 64;
            uint32_t off = SW128((uint32_t)((rr + p * 64) * 128 + cg * 2));
            if (gr < NN)
                cp16(base + off, A + (size_t)gr * KTOT + k0 + cg);
            else
                *reinterpret_cast<uint4*>(smem + s * STG + off) = make_uint4(0, 0, 0, 0);
        }
    };
    auto cpB = [&](int ch, int s) {
        int k0 = ch * 64;
        uint32_t base = sb + s * STG;
        #pragma unroll
        for (int p = 0; p < NT / 64; ++p) {
            int n = rr + p * 64;
            size_t go = (size_t)n * KTOT + k0 + cg;
            uint32_t off = SW128((uint32_t)(n * 128 + cg * 2));
            cp16(base + OF_B + off, W + go);
        }
    };
    auto domma = [&](int s) {
        uint32_t aF = sb + s * STG;
        uint32_t bF = aF + OF_B;
        #pragma unroll
        for (int ks = 0; ks < 4; ++ks) {
            int kk = ks * 16;
            uint32_t af[2][4];
            #pragma unroll
            for (int mi = 0; mi < 2; ++mi) {
                int r = wm * 32 + mi * 16 + (lane & 15);
                int c = kk + (lane >> 4) * 8;
                uint32_t off = SW128((uint32_t)(r * 128 + c * 2));
                ldm_x4(af[mi], aF + off);
            }
            #pragma unroll
            for (int nt = 0; nt < NI / 2; ++nt) {
                int g = lane >> 3;
                int row = wn * NPW + nt * 16 + (g >> 1) * 8 + (lane & 7);
                int c = kk + (g & 1) * 8;
                uint32_t off = SW128((uint32_t)(row * 128 + c * 2));
                uint32_t bh[4];
                ldm_x4(bh, bF + off);
                #pragma unroll
                for (int half = 0; half < 2; ++half) {
                    int ni = nt * 2 + half;
                    #pragma unroll
                    for (int mi = 0; mi < 2; ++mi)
                        mma_f16(acc[mi][ni], af[mi], bh[half * 2], bh[half * 2 + 1]);
                }
            }
        }
    };

    if (BN) ldgA(0); else cpA(0, 0);
    cpB(0, 0);
    CP_COMMIT();
    if (BN) stsA(0, 0);

    for (int ch = 0; ch < KCH; ++ch) {
        int s = ch & 1;
        CP_WAIT0();
        __syncthreads();
        if (ch + 1 < KCH) {
            if (BN) ldgA(ch + 1); else cpA(ch + 1, s ^ 1);
            cpB(ch + 1, s ^ 1);
            CP_COMMIT();
        }
        domma(s);
        if (BN && ch + 1 < KCH) stsA(ch + 1, s ^ 1);
    }

    // epilogue: fp16 store (x dinv if SCALE)
    #pragma unroll
    for (int mi = 0; mi < 2; ++mi) {
        int r0 = rowBase + wm * 32 + mi * 16 + (lane >> 2);
        int r1 = r0 + 8;
        float d0 = 1.f, d1 = 1.f;
        if (SCALE) {
            d0 = (r0 < NN) ? g_dinv[r0] : 0.f;
            d1 = (r1 < NN) ? g_dinv[r1] : 0.f;
        }
        #pragma unroll
        for (int ni = 0; ni < NI; ++ni) {
            int c0 = wn * NPW + ni * 8 + (lane & 3) * 2;
            if (r0 < NN)
                *reinterpret_cast<__half2*>(C + (size_t)r0 * NT + c0) =
                    __floats2half2_rn(acc[mi][ni][0] * d0, acc[mi][ni][1] * d0);
            if (r1 < NN)
                *reinterpret_cast<__half2*>(C + (size_t)r1 * NT + c0) =
                    __floats2half2_rn(acc[mi][ni][2] * d1, acc[mi][ni][3] * d1);
        }
    }

    // fused BN stats (layer-0 GEMM): fp32 accumulators, padding rows are zero
    if constexpr (STATS) {
        __shared__ float s_sum[256];
        __shared__ float s_sq[256];
        if (tid < 256) { s_sum[tid] = 0.f; s_sq[tid] = 0.f; }
        __syncthreads();
        #pragma unroll
        for (int ni = 0; ni < NI; ++ni) {
            float s0 = 0.f, q0 = 0.f, s1 = 0.f, q1 = 0.f;
            #pragma unroll
            for (int mi = 0; mi < 2; ++mi) {
                float va = acc[mi][ni][0], vb = acc[mi][ni][2];
                s0 += va + vb; q0 += va * va + vb * vb;
                float vc = acc[mi][ni][1], vd = acc[mi][ni][3];
                s1 += vc + vd; q1 += vc * vc + vd * vd;
            }
            #pragma unroll
            for (int off = 4; off <= 16; off <<= 1) {
                s0 += __shfl_xor_sync(0xffffffffu, s0, off);
                q0 += __shfl_xor_sync(0xffffffffu, q0, off);
                s1 += __shfl_xor_sync(0xffffffffu, s1, off);
                q1 += __shfl_xor_sync(0xffffffffu, q1, off);
            }
            if ((lane >> 2) == 0) {
                int c0 = wn * NPW + ni * 8 + (lane & 3) * 2;
                atomicAdd(&s_sum[c0], s0);
                atomicAdd(&s_sq[c0], q0);
                atomicAdd(&s_sum[c0 + 1], s1);
                atomicAdd(&s_sq[c0 + 1], q1);
            }
        }
        __syncthreads();
        if (tid < 256) {
            atomicAdd(&g_sum[tid], s_sum[tid]);
            atomicAdd(&g_sumsq[tid], s_sq[tid]);
        }
    }
}

// ---------------- SpMM fp16 in -> fp16 out (+fp32 stats) --------------------
template <bool WEIGHTED, bool STATS, int COLS>
__global__ __launch_bounds__(512)
void spmmh_kernel(const __half* __restrict__ in, __half* __restrict__ out) {
    constexpr int CPL = COLS / 32;
    int warp = threadIdx.x >> 5, lane = threadIdx.x & 31;
    int row = blockIdx.x * 16 + warp;

    float acc[CPL];
    {
        const __half2* p = reinterpret_cast<const __half2*>(in + (size_t)row * COLS + lane * CPL);
        float w = WEIGHTED ? g_dinv[row] : 1.f;
        #pragma unroll
        for (int j = 0; j < CPL / 2; ++j) {
            float2 f = __half22float2(p[j]);
            acc[j * 2] = f.x * w;
            acc[j * 2 + 1] = f.y * w;
        }
    }
    int s = g_rowptr[row], e = g_rowptr[row + 1];
    for (int i = s; i < e; ++i) {
        int c = g_col[i];
        const __half* p = in + (size_t)c * COLS + lane * CPL;
        float w = WEIGHTED ? g_dinv[c] : 1.f;
        if constexpr (CPL == 8) {
            uint4 u = *reinterpret_cast<const uint4*>(p);
            __half2* hp = reinterpret_cast<__half2*>(&u);
            #pragma unroll
            for (int j = 0; j < 4; ++j) {
                float2 f = __half22float2(hp[j]);
                if (WEIGHTED) {
                    acc[j * 2] = fmaf(f.x, w, acc[j * 2]);
                    acc[j * 2 + 1] = fmaf(f.y, w, acc[j * 2 + 1]);
                } else {
                    acc[j * 2] += f.x;
                    acc[j * 2 + 1] += f.y;
                }
            }
        } else {
            uint2 u = *reinterpret_cast<const uint2*>(p);
            __half2* hp = reinterpret_cast<__half2*>(&u);
            #pragma unroll
            for (int j = 0; j < 2; ++j) {
                float2 f = __half22float2(hp[j]);
                if (WEIGHTED) {
                    acc[j * 2] = fmaf(f.x, w, acc[j * 2]);
                    acc[j * 2 + 1] = fmaf(f.y, w, acc[j * 2 + 1]);
                } else {
                    acc[j * 2] += f.x;
                    acc[j * 2 + 1] += f.y;
                }
            }
        }
    }
    float d = g_dinv[row];
    #pragma unroll
    for (int j = 0; j < CPL; ++j) acc[j] *= d;

    {
        __half2 o[CPL / 2];
        #pragma unroll
        for (int j = 0; j < CPL / 2; ++j)
            o[j] = __floats2half2_rn(acc[j * 2], acc[j * 2 + 1]);
        __half* op = out + (size_t)row * COLS + lane * CPL;
        if constexpr (CPL == 8)
            *reinterpret_cast<uint4*>(op) = *reinterpret_cast<uint4*>(o);
        else
            *reinterpret_cast<uint2*>(op) = *reinterpret_cast<uint2*>(o);
    }

    if constexpr (STATS) {
        __shared__ float ss[16][COLS];
        __shared__ float sq[16][COLS];
        #pragma unroll
        for (int j = 0; j < CPL; ++j) {
            ss[warp][lane * CPL + j] = acc[j];
            sq[warp][lane * CPL + j] = acc[j] * acc[j];
        }
        __syncthreads();
        int t = threadIdx.x;
        if (t < COLS) {
            float sm = 0.f;
            #pragma unroll
            for (int w = 0; w < 16; ++w) sm += ss[w][t];
            atomicAdd(&g_sum[t], sm);
        } else if (t < 2 * COLS) {
            int c = t - COLS;
            float sm = 0.f;
            #pragma unroll
            for (int w = 0; w < 16; ++w) sm += sq[w][c];
            atomicAdd(&g_sumsq[c], sm);
        }
    }
}

// ---------------- BN finalize (+reset stats for graph-replay determinism) ---
__global__ void bn_finalize_kernel(const float* __restrict__ gamma,
                                   const float* __restrict__ beta) {
    int c = threadIdx.x;
    float mu = g_sum[c] * (1.f / NN);
    float var = g_sumsq[c] * (1.f / NN) - mu * mu;
    float sc = rsqrtf(var + 1e-5f) * gamma[c];
    g_scale[c] = sc;
    g_shift[c] = beta[c] - mu * sc;
    g_sum[c] = 0.f;
    g_sumsq[c] = 0.f;
}

// ---------------- final SpMM (64-stride fp16 in, 40 cols) + log_softmax -----
__global__ __launch_bounds__(256)
void spmm40_softmax_kernel(const __half* __restrict__ hs,
                           const float* __restrict__ bl,
                           float* __restrict__ out) {
    int warp = threadIdx.x >> 5, lane = threadIdx.x & 31;
    int row = blockIdx.x * 8 + warp;
    if (row >= NN) return;
    size_t rbase = (size_t)row * 64;
    float a0 = __half2float(hs[rbase + lane]);
    float a1 = (lane < 8) ? __half2float(hs[rbase + 32 + lane]) : 0.f;
    int s = g_rowptr[row], e = g_rowptr[row + 1];
    for (int i = s; i < e; ++i) {
        size_t cb = (size_t)g_col[i] * 64;
        a0 += __half2float(hs[cb + lane]);
        if (lane < 8) a1 += __half2float(hs[cb + 32 + lane]);
    }
    float d = g_dinv[row];
    float v0 = fmaf(a0, d, bl[lane]);
    float v1 = (lane < 8) ? fmaf(a1, d, bl[32 + lane]) : 0.f;

    float m = v0;
    if (lane < 8) m = fmaxf(m, v1);
    #pragma unroll
    for (int off = 16; off > 0; off >>= 1)
        m = fmaxf(m, __shfl_xor_sync(0xffffffffu, m, off));
    float sum = expf(v0 - m) + ((lane < 8) ? expf(v1 - m) : 0.f);
    #pragma unroll
    for (int off = 16; off > 0; off >>= 1)
        sum += __shfl_xor_sync(0xffffffffu, sum, off);
    float lse = logf(sum);
    size_t ob = (size_t)row * D_O;
    out[ob + lane] = v0 - m - lse;
    if (lane < 8) out[ob + 32 + lane] = v1 - m - lse;
}

// ---------------- launcher ---------------------------------------------------
extern "C" void kernel_launch(void* const* d_in, const int* in_sizes, int n_in,
                              void* d_out, int out_size) {
    const float* x     = (const float*)d_in[0];
    const float* W0    = (const float*)d_in[1];
    const float* Wh    = (const float*)d_in[3];
    const float* gamma = (const float*)d_in[5];
    const float* beta  = (const float*)d_in[6];
    const float* Wl    = (const float*)d_in[7];
    const float* bl    = (const float*)d_in[8];
    const int*   ei    = (const int*)d_in[9];
    const int* rowE = ei;
    const int* colE = ei + NE;
    float* out = (float*)d_out;

    __half *pHA, *pHB, *w0, *wh, *wl;
    cudaGetSymbolAddress((void**)&pHA, g_bufHA);
    cudaGetSymbolAddress((void**)&pHB, g_bufHB);
    cudaGetSymbolAddress((void**)&w0, g_w0);
    cudaGetSymbolAddress((void**)&wh, g_wh);
    cudaGetSymbolAddress((void**)&wl, g_wl);

    constexpr int SMEM256 = 2 * (16384 + 256 * 128);  // 98304
    constexpr int SMEM64  = 2 * (16384 + 64 * 128);   // 49152
    cudaFuncSetAttribute(gemm_mma_kernel<128, 256, false, false, true>,
                         cudaFuncAttributeMaxDynamicSharedMemorySize, SMEM256);
    cudaFuncSetAttribute(gemm_mma_kernel<256, 256, true, true, false>,
                         cudaFuncAttributeMaxDynamicSharedMemorySize, SMEM256);
    cudaFuncSetAttribute(gemm_mma_kernel<256, 64, true, true, false>,
                         cudaFuncAttributeMaxDynamicSharedMemorySize, SMEM64);

    const int EB = (NE + 255) / 256;
    const int NBLK = (NN + 255) / 256;
    const int MT = (NN + 127) / 128;
    const int SPB = NN / 16;

    // prep
    convert_w_all_kernel<<<(CVT_TOTAL + 255) / 256, 256>>>(W0, Wh, Wl);
    convert_x_kernel<<<(NN * 32 + 255) / 256, 256>>>(x, pHA);
    count_deg_kernel<<<EB, 256>>>(rowE);
    scan1_kernel<<<SCAN_BLOCKS, 1024>>>();
    scan2_kernel<<<1, 128>>>();
    scan3_kernel<<<NBLK, 256>>>();
    fill_csr_kernel<<<EB, 256>>>(rowE, colE);

    // layer 0: weighted fp16 aggregate of x -> GEMM (cp.async A) + BN stats
    spmmh_kernel<true, false, 128><<<SPB, 512>>>(pHA, pHB);
    gemm_mma_kernel<128, 256, false, false, true><<<MT, 512, SMEM256>>>(pHB, w0, pHA);
    bn_finalize_kernel<<<1, 256>>>(gamma, beta);

    // hidden layers 1..3: GEMM(BN fold, dinv) -> SpMM(+stats), all fp16
    for (int l = 0; l < 3; ++l) {
        gemm_mma_kernel<256, 256, true, true, false><<<MT, 512, SMEM256>>>(
            pHA, wh + (size_t)l * 65536, pHB);
        spmmh_kernel<false, true, 256><<<SPB, 512>>>(pHB, pHA);
        bn_finalize_kernel<<<1, 256>>>(gamma + (size_t)(l + 1) * D_H,
                                       beta + (size_t)(l + 1) * D_H);
    }

    // final layer (fp16 logits, BN3 fold + dinv) + softmax SpMM
    gemm_mma_kernel<256, 64, true, true, false><<<MT, 512, SMEM64>>>(pHA, wl, pHB);
    spmm40_softmax_kernel<<<NN / 8, 256>>>(pHB, bl, out);
}